// round 2
// baseline (speedup 1.0000x reference)
#include <cuda_runtime.h>

#define BB   2
#define T1   2048
#define T2V  2048
#define CC   512
#define HH   8
#define DD   64
#define NSRC 3

// Static scratch (allocation-free rule): Q, K(3), V(3), O accumuldel
__device__ float g_q[BB * T1 * CC];          // 8 MB
__device__ float g_k[NSRC * BB * T2V * CC];  // 24 MB
__device__ float g_v[NSRC * BB * T2V * CC];  // 24 MB
__device__ float g_o[BB * T1 * CC];          // 8 MB

// ---------------------------------------------------------------------------
// GEMM: out[m][n] = scale * (sum_k A[m][k]*W[k][n] + bias[n])
// A: [M,512] row-major, W: [512,512] row-major, M = 4096 always here.
// Tile 128x128x8, 256 threads, 8x8 per thread, double-buffered smem.
// ---------------------------------------------------------------------------
__global__ __launch_bounds__(256) void gemm512(
    const float* __restrict__ A, const float* __restrict__ W,
    const float* __restrict__ bias, float* __restrict__ out, float scale)
{
    __shared__ float As[2][8][128];   // [k][m]
    __shared__ float Bs[2][8][128];   // [k][n]

    const int tid = threadIdx.x;
    const int bm = blockIdx.y * 128;
    const int bn = blockIdx.x * 128;

    const int a_r = tid >> 1;            // 0..127
    const int a_k = (tid & 1) * 4;       // 0 or 4
    const int b_k = tid >> 5;            // 0..7
    const int b_n = (tid & 31) * 4;      // 0..124
    const int ty  = tid >> 4;            // 0..15
    const int tx  = tid & 15;            // 0..15

    float acc[8][8];
#pragma unroll
    for (int i = 0; i < 8; i++)
#pragma unroll
        for (int j = 0; j < 8; j++) acc[i][j] = 0.0f;

    // prologue: tile 0
    float4 av = *(const float4*)(A + (size_t)(bm + a_r) * CC + a_k);
    float4 bv = *(const float4*)(W + (size_t)b_k * CC + bn + b_n);
    As[0][a_k + 0][a_r] = av.x;
    As[0][a_k + 1][a_r] = av.y;
    As[0][a_k + 2][a_r] = av.z;
    As[0][a_k + 3][a_r] = av.w;
    *(float4*)&Bs[0][b_k][b_n] = bv;
    __syncthreads();

    int buf = 0;
    for (int kt = 0; kt < 64; kt++) {
        if (kt < 63) {
            av = *(const float4*)(A + (size_t)(bm + a_r) * CC + (kt + 1) * 8 + a_k);
            bv = *(const float4*)(W + (size_t)((kt + 1) * 8 + b_k) * CC + bn + b_n);
        }
#pragma unroll
        for (int k = 0; k < 8; k++) {
            float a[8], bb[8];
            *(float4*)&a[0]  = *(const float4*)&As[buf][k][ty * 8];
            *(float4*)&a[4]  = *(const float4*)&As[buf][k][ty * 8 + 4];
            *(float4*)&bb[0] = *(const float4*)&Bs[buf][k][tx * 8];
            *(float4*)&bb[4] = *(const float4*)&Bs[buf][k][tx * 8 + 4];
#pragma unroll
            for (int i = 0; i < 8; i++)
#pragma unroll
                for (int j = 0; j < 8; j++)
                    acc[i][j] += a[i] * bb[j];
        }
        if (kt < 63) {
            buf ^= 1;
            As[buf][a_k + 0][a_r] = av.x;
            As[buf][a_k + 1][a_r] = av.y;
            As[buf][a_k + 2][a_r] = av.z;
            As[buf][a_k + 3][a_r] = av.w;
            *(float4*)&Bs[buf][b_k][b_n] = bv;
            __syncthreads();
        }
    }

    float bcol[8];
    *(float4*)&bcol[0] = *(const float4*)(bias + bn + tx * 8);
    *(float4*)&bcol[4] = *(const float4*)(bias + bn + tx * 8 + 4);

#pragma unroll
    for (int i = 0; i < 8; i++) {
        float4 o0, o1;
        o0.x = scale * (acc[i][0] + bcol[0]);
        o0.y = scale * (acc[i][1] + bcol[1]);
        o0.z = scale * (acc[i][2] + bcol[2]);
        o0.w = scale * (acc[i][3] + bcol[3]);
        o1.x = scale * (acc[i][4] + bcol[4]);
        o1.y = scale * (acc[i][5] + bcol[5]);
        o1.z = scale * (acc[i][6] + bcol[6]);
        o1.w = scale * (acc[i][7] + bcol[7]);
        float* op = out + (size_t)(bm + ty * 8 + i) * CC + bn + tx * 8;
        *(float4*)op       = o0;
        *(float4*)(op + 4) = o1;
    }
}

// ---------------------------------------------------------------------------
// Flash attention, fp32. One block = one (b, h, 64-row Q tile). Loops the 3
// KV sources internally, each with its own online softmax; accumulates
// sum_i softmax(QK_i^T)V_i into registers, writes O once.
// 256 threads as 16x16; each thread owns a 4x4 micro-tile.
// smem: Qts[d][r], Kts[d][c], Vs[c][d], Pts[c][r]  (all 64x68 padded)
// ---------------------------------------------------------------------------
#define SPAD 68
#define ATTN_SMEM (4 * 64 * SPAD * 4)

__global__ __launch_bounds__(256) void attn64(
    const float* __restrict__ gq, const float* __restrict__ gk,
    const float* __restrict__ gv, float* __restrict__ go)
{
    extern __shared__ float sm[];
    float (*Qts)[SPAD] = (float(*)[SPAD])(sm);
    float (*Kts)[SPAD] = (float(*)[SPAD])(sm + 64 * SPAD);
    float (*Vs)[SPAD]  = (float(*)[SPAD])(sm + 2 * 64 * SPAD);
    float (*Pts)[SPAD] = (float(*)[SPAD])(sm + 3 * 64 * SPAD);

    const int tid = threadIdx.x;
    const int ty = tid >> 4;        // 0..15 -> Q rows ty*4..+4
    const int tx = tid & 15;        // 0..15 -> cols  tx*4..+4
    const int qt0 = blockIdx.x * 64;
    const int h = blockIdx.y;
    const int b = blockIdx.z;

    const int lr = tid >> 2;        // 0..63 tile row for loads
    const int lc = (tid & 3) * 4;   // 0,4,8,12

    // Q tile (already pre-scaled by 1/8 in the GEMM), stored transposed [d][r]
    {
        const float* qp = gq + ((size_t)(b * T1 + qt0 + lr)) * CC + h * DD;
#pragma unroll
        for (int q4 = 0; q4 < 4; q4++) {
            int d = lc + q4 * 16;
            float4 v = *(const float4*)(qp + d);
            Qts[d + 0][lr] = v.x;
            Qts[d + 1][lr] = v.y;
            Qts[d + 2][lr] = v.z;
            Qts[d + 3][lr] = v.w;
        }
    }

    float oacc[16];
#pragma unroll
    for (int i = 0; i < 16; i++) oacc[i] = 0.0f;

    for (int src = 0; src < NSRC; src++) {
        const float* K = gk + ((size_t)(src * BB + b)) * T2V * CC + h * DD;
        const float* V = gv + ((size_t)(src * BB + b)) * T2V * CC + h * DD;

        float o[16];
#pragma unroll
        for (int i = 0; i < 16; i++) o[i] = 0.0f;
        float mrow[4] = {-1e30f, -1e30f, -1e30f, -1e30f};
        float lrow[4] = {0.0f, 0.0f, 0.0f, 0.0f};

        for (int kt = 0; kt < T2V / 64; kt++) {
            __syncthreads();   // previous tile's Pts/Vs fully consumed; Q visible
            {
                const float* kp = K + (size_t)(kt * 64 + lr) * CC;
                const float* vp = V + (size_t)(kt * 64 + lr) * CC;
#pragma unroll
                for (int q4 = 0; q4 < 4; q4++) {
                    int d = lc + q4 * 16;
                    float4 kv = *(const float4*)(kp + d);
                    Kts[d + 0][lr] = kv.x;
                    Kts[d + 1][lr] = kv.y;
                    Kts[d + 2][lr] = kv.z;
                    Kts[d + 3][lr] = kv.w;
                    float4 vv = *(const float4*)(vp + d);
                    *(float4*)&Vs[lr][d] = vv;
                }
            }
            __syncthreads();

            // S = Q K^T (4x4 micro-tile per thread)
            float s[4][4];
#pragma unroll
            for (int j = 0; j < 4; j++)
#pragma unroll
                for (int jj = 0; jj < 4; jj++) s[j][jj] = 0.0f;

#pragma unroll
            for (int k = 0; k < 64; k++) {
                float4 a  = *(const float4*)&Qts[k][ty * 4];
                float4 bb = *(const float4*)&Kts[k][tx * 4];
                s[0][0] += a.x * bb.x; s[0][1] += a.x * bb.y; s[0][2] += a.x * bb.z; s[0][3] += a.x * bb.w;
                s[1][0] += a.y * bb.x; s[1][1] += a.y * bb.y; s[1][2] += a.y * bb.z; s[1][3] += a.y * bb.w;
                s[2][0] += a.z * bb.x; s[2][1] += a.z * bb.y; s[2][2] += a.z * bb.z; s[2][3] += a.z * bb.w;
                s[3][0] += a.w * bb.x; s[3][1] += a.w * bb.y; s[3][2] += a.w * bb.z; s[3][3] += a.w * bb.w;
            }

            // online softmax per row; row reduction across the 16 tx lanes
#pragma unroll
            for (int j = 0; j < 4; j++) {
                float mt = fmaxf(fmaxf(s[j][0], s[j][1]), fmaxf(s[j][2], s[j][3]));
#pragma unroll
                for (int w = 1; w < 16; w <<= 1)
                    mt = fmaxf(mt, __shfl_xor_sync(0xffffffffu, mt, w));
                float mnew = fmaxf(mrow[j], mt);
                float corr = __expf(mrow[j] - mnew);
                mrow[j] = mnew;
                lrow[j] *= corr;
                o[j * 4 + 0] *= corr;
                o[j * 4 + 1] *= corr;
                o[j * 4 + 2] *= corr;
                o[j * 4 + 3] *= corr;
                float ps = 0.0f;
#pragma unroll
                for (int jj = 0; jj < 4; jj++) {
                    float p = __expf(s[j][jj] - mnew);
                    ps += p;
                    Pts[tx * 4 + jj][ty * 4 + j] = p;   // transposed for PV
                }
#pragma unroll
                for (int w = 1; w < 16; w <<= 1)
                    ps += __shfl_xor_sync(0xffffffffu, ps, w);
                lrow[j] += ps;
            }
            __syncthreads();

            // O += P V
#pragma unroll
            for (int c = 0; c < 64; c++) {
                float4 p = *(const float4*)&Pts[c][ty * 4];
                float4 v = *(const float4*)&Vs[c][tx * 4];
                o[0]  += p.x * v.x; o[1]  += p.x * v.y; o[2]  += p.x * v.z; o[3]  += p.x * v.w;
                o[4]  += p.y * v.x; o[5]  += p.y * v.y; o[6]  += p.y * v.z; o[7]  += p.y * v.w;
                o[8]  += p.z * v.x; o[9]  += p.z * v.y; o[10] += p.z * v.z; o[11] += p.z * v.w;
                o[12] += p.w * v.x; o[13] += p.w * v.y; o[14] += p.w * v.z; o[15] += p.w * v.w;
            }
        }

#pragma unroll
        for (int j = 0; j < 4; j++) {
            float inv = 1.0f / lrow[j];
#pragma unroll
            for (int jj = 0; jj < 4; jj++)
                oacc[j * 4 + jj] += o[j * 4 + jj] * inv;
        }
    }

#pragma unroll
    for (int j = 0; j < 4; j++) {
        float4 w4 = make_float4(oacc[j * 4 + 0], oacc[j * 4 + 1],
                                oacc[j * 4 + 2], oacc[j * 4 + 3]);
        *(float4*)(go + ((size_t)(b * T1 + qt0 + ty * 4 + j)) * CC + h * DD + tx * 4) = w4;
    }
}

// ---------------------------------------------------------------------------
extern "C" void kernel_launch(void* const* d_in, const int* in_sizes, int n_in,
                              void* d_out, int out_size)
{
    const float* x  = (const float*)d_in[0];
    const float* y  = (const float*)d_in[1];
    const float* Wq = (const float*)d_in[2];
    const float* bq = (const float*)d_in[3];
    const float* Wk = (const float*)d_in[4];
    const float* bk = (const float*)d_in[5];
    const float* Wv = (const float*)d_in[6];
    const float* bv = (const float*)d_in[7];
    const float* Wp = (const float*)d_in[8];
    const float* bp = (const float*)d_in[9];
    float* out = (float*)d_out;

    float *pq, *pk, *pv, *po;
    cudaGetSymbolAddress((void**)&pq, g_q);
    cudaGetSymbolAddress((void**)&pk, g_k);
    cudaGetSymbolAddress((void**)&pv, g_v);
    cudaGetSymbolAddress((void**)&po, g_o);

    cudaFuncSetAttribute(attn64, cudaFuncAttributeMaxDynamicSharedMemorySize,
                         ATTN_SMEM);

    dim3 gg(CC / 128, (BB * T1) / 128);   // (4, 32)
    dim3 gb(256);

    // Q projection, pre-scaled by 1/sqrt(D) = 1/8
    gemm512<<<gg, gb>>>(x, Wq, bq, pq, 0.125f);

    // K/V projections for each of the 3 sources
    for (int i = 0; i < NSRC; i++) {
        const float* yi = y + (size_t)i * BB * T2V * CC;
        gemm512<<<gg, gb>>>(yi, Wk + (size_t)i * CC * CC, bk + i * CC,
                            pk + (size_t)i * BB * T2V * CC, 1.0f);
        gemm512<<<gg, gb>>>(yi, Wv + (size_t)i * CC * CC, bv + i * CC,
                            pv + (size_t)i * BB * T2V * CC, 1.0f);
    }

    // Attention (loops 3 sources internally)
    attn64<<<dim3(T1 / 64, HH, BB), 256, ATTN_SMEM>>>(pq, pk, pv, po);

    // Output projection -> d_out
    gemm512<<<gg, gb>>>(po, Wp, bp, out, 1.0f);
}

// round 6
// speedup vs baseline: 1.2190x; 1.2190x over previous
#include <cuda_runtime.h>
#include <cuda_bf16.h>
#include <stdint.h>

#define NSRC 3
#define ELEM_X (2*2048*512)
#define ELEM_Y (3*2*2048*512)
#define WSTR   (512*512)

// bf16 split inputs/weights
__device__ __nv_bfloat16 g_xh[ELEM_X], g_xl[ELEM_X];
__device__ __nv_bfloat16 g_yh[ELEM_Y], g_yl[ELEM_Y];
__device__ __nv_bfloat16 g_wh[8*WSTR], g_wl[8*WSTR];
// fp32 intermediates (SIMT attention this round)
__device__ float g_q[ELEM_X];
__device__ float g_k[ELEM_Y];
__device__ float g_v[ELEM_Y];
__device__ float g_o[ELEM_X];
__device__ __nv_bfloat16 g_oh[ELEM_X], g_ol[ELEM_X];

#define SWZ(o) ((uint32_t)(o) ^ ((((uint32_t)(o)) >> 3) & 0x70u))
#define ID_128 0x8200490u   /* kind::f16, f32 acc, bf16xbf16, M=128, N=128 */

#if defined(__CUDA_ARCH_FEAT_SM103_ALL) || defined(__CUDA_ARCH_FEAT_SM100_ALL) || !defined(__CUDA_ARCH__)
#define HAS_TC5 1
#else
#define HAS_TC5 0
#endif

__device__ __forceinline__ uint32_t elect1() {
    uint32_t p;
    asm volatile("{\n\t.reg .pred p;\n\telect.sync _|p, 0xFFFFFFFF;\n\tselp.b32 %0,1,0,p;\n\t}" : "=r"(p));
    return p;
}
__device__ __forceinline__ uint32_t s2u(const void* p) {
    uint32_t a;
    asm("{ .reg .u64 t; cvta.to.shared.u64 t, %1; cvt.u32.u64 %0, t; }" : "=r"(a) : "l"(p));
    return a;
}
__device__ __forceinline__ uint64_t dk(uint32_t a) {   // K-major SW128 desc
    return (2ull<<61)|(1ull<<46)|(64ull<<32)|(1ull<<16)|((uint64_t)(a>>4)&0x3FFFull);
}

#define MBAR_INIT(a,n) asm volatile("mbarrier.init.shared.b64 [%0], %1;" :: "r"(a), "r"(n) : "memory")
#define MBAR_WAIT(a,ph) asm volatile("{\n\t.reg .pred P1;\n\tLW%=:\n\t" \
    "mbarrier.try_wait.parity.acquire.cta.shared::cta.b64 P1, [%0], %1, 0x989680;\n\t" \
    "@P1 bra.uni LD%=;\n\tbra.uni LW%=;\n\tLD%=:\n\t}" :: "r"(a), "r"(ph) : "memory")
#define FPROXY()       asm volatile("fence.proxy.async.shared::cta;" ::: "memory")

#if HAS_TC5
__device__ __forceinline__ void mma16(uint32_t d, uint64_t a, uint64_t b, uint32_t id, uint32_t acc) {
    asm volatile("{\n\t.reg .pred p;\n\tsetp.ne.u32 p, %4, 0;\n\t"
        "tcgen05.mma.cta_group::1.kind::f16 [%0], %1, %2, %3, {%5,%5,%5,%5}, p;\n\t}"
        :: "r"(d), "l"(a), "l"(b), "r"(id), "r"(acc), "r"(0u) : "memory");
}
#define TC_ALLOC(a,n)  asm volatile("tcgen05.alloc.cta_group::1.sync.aligned.shared::cta.b32 [%0], %1;" :: "r"(a), "r"(n) : "memory")
#define TC_RELQ()      asm volatile("tcgen05.relinquish_alloc_permit.cta_group::1.sync.aligned;")
#define TC_DEALLOC(t,n) asm volatile("tcgen05.dealloc.cta_group::1.sync.aligned.b32 %0, %1;" :: "r"(t), "r"(n))
#define TC_COMMIT(a)   asm volatile("tcgen05.commit.cta_group::1.mbarrier::arrive::one.shared::cluster.b64 [%0];" :: "r"(a) : "memory")
#define TC_FA()        asm volatile("tcgen05.fence::after_thread_sync;" ::: "memory")
#define TC_FB()        asm volatile("tcgen05.fence::before_thread_sync;" ::: "memory")
#define TC_WLD()       asm volatile("tcgen05.wait::ld.sync.aligned;" ::: "memory")
#define LDTM32(r, a) asm volatile( \
    "tcgen05.ld.sync.aligned.32x32b.x32.b32 " \
    "{%0,%1,%2,%3,%4,%5,%6,%7,%8,%9,%10,%11,%12,%13,%14,%15," \
    "%16,%17,%18,%19,%20,%21,%22,%23,%24,%25,%26,%27,%28,%29,%30,%31}, [%32];" \
    : "=r"((r)[0]),"=r"((r)[1]),"=r"((r)[2]),"=r"((r)[3]),"=r"((r)[4]),"=r"((r)[5]),"=r"((r)[6]),"=r"((r)[7]), \
      "=r"((r)[8]),"=r"((r)[9]),"=r"((r)[10]),"=r"((r)[11]),"=r"((r)[12]),"=r"((r)[13]),"=r"((r)[14]),"=r"((r)[15]), \
      "=r"((r)[16]),"=r"((r)[17]),"=r"((r)[18]),"=r"((r)[19]),"=r"((r)[20]),"=r"((r)[21]),"=r"((r)[22]),"=r"((r)[23]), \
      "=r"((r)[24]),"=r"((r)[25]),"=r"((r)[26]),"=r"((r)[27]),"=r"((r)[28]),"=r"((r)[29]),"=r"((r)[30]),"=r"((r)[31]) \
    : "r"(a))
#else
__device__ __forceinline__ void mma16(uint32_t, uint64_t, uint64_t, uint32_t, uint32_t) { __trap(); }
#define TC_ALLOC(a,n)   __trap()
#define TC_RELQ()       __trap()
#define TC_DEALLOC(t,n) __trap()
#define TC_COMMIT(a)    __trap()
#define TC_FA()         ((void)0)
#define TC_FB()         ((void)0)
#define TC_WLD()        ((void)0)
#define LDTM32(r, a) do { _Pragma("unroll") for (int _i = 0; _i < 32; _i++) (r)[_i] = 0u; __trap(); } while (0)
#endif

__device__ __forceinline__ uint32_t packh(__nv_bfloat16 a, __nv_bfloat16 b) {
    __nv_bfloat162 v; v.x = a; v.y = b;
    return *reinterpret_cast<uint32_t*>(&v);
}

// ------------------------- prep kernels -----------------------------------
__global__ void splitk(const float* __restrict__ in, __nv_bfloat16* __restrict__ oh,
                       __nv_bfloat16* __restrict__ ol, int n4) {
    for (int i = blockIdx.x * blockDim.x + threadIdx.x; i < n4; i += gridDim.x * blockDim.x) {
        float4 v = ((const float4*)in)[i];
        __nv_bfloat16 h0 = __float2bfloat16_rn(v.x), h1 = __float2bfloat16_rn(v.y);
        __nv_bfloat16 h2 = __float2bfloat16_rn(v.z), h3 = __float2bfloat16_rn(v.w);
        __nv_bfloat16 l0 = __float2bfloat16_rn(v.x - __bfloat162float(h0));
        __nv_bfloat16 l1 = __float2bfloat16_rn(v.y - __bfloat162float(h1));
        __nv_bfloat16 l2 = __float2bfloat16_rn(v.z - __bfloat162float(h2));
        __nv_bfloat16 l3 = __float2bfloat16_rn(v.w - __bfloat162float(h3));
        *(uint2*)(oh + 4 * (size_t)i) = make_uint2(packh(h0, h1), packh(h2, h3));
        *(uint2*)(ol + 4 * (size_t)i) = make_uint2(packh(l0, l1), packh(l2, l3));
    }
}

__global__ void wtsk(const float* __restrict__ W, __nv_bfloat16* __restrict__ th,
                     __nv_bfloat16* __restrict__ tl) {
    __shared__ float t[32][33];
    int m = blockIdx.z;
    int k0 = blockIdx.x * 32, n0 = blockIdx.y * 32;
    const float* Wm = W + (size_t)m * WSTR;
    t[threadIdx.y][threadIdx.x] = Wm[(size_t)(k0 + threadIdx.y) * 512 + n0 + threadIdx.x];
    __syncthreads();
    float v = t[threadIdx.x][threadIdx.y];
    size_t di = (size_t)m * WSTR + (size_t)(n0 + threadIdx.y) * 512 + k0 + threadIdx.x;
    __nv_bfloat16 h = __float2bfloat16_rn(v);
    th[di] = h;
    tl[di] = __float2bfloat16_rn(v - __bfloat162float(h));
}

// ------------------------- tcgen05 GEMM (fp32 out) -------------------------
__global__ __launch_bounds__(256) void tgemm(
    const __nv_bfloat16* __restrict__ ah, const __nv_bfloat16* __restrict__ al,
    const __nv_bfloat16* __restrict__ bh, const __nv_bfloat16* __restrict__ bl,
    const float* __restrict__ bias, float* __restrict__ of, float scale)
{
    extern __shared__ char sm[];
    const uint32_t sb = s2u(sm);
    const int tid = threadIdx.x, wid = tid >> 5, lane = tid & 31;
    const int bm = blockIdx.y * 128, bn = blockIdx.x * 128;

    if (wid == 0) { TC_ALLOC(sb, 128); TC_RELQ(); }
    if (tid == 0) { MBAR_INIT(sb + 8, 1); MBAR_INIT(sb + 16, 1); }
    __syncthreads();
    uint32_t tm;
    asm volatile("ld.shared.b32 %0, [%1];" : "=r"(tm) : "r"(sb));

    auto stage = [&](int kc, int buf) {
#pragma unroll
        for (int i = 0; i < 16; i++) {
            int idx = tid + i * 256;
            int t = idx >> 10, r = (idx >> 3) & 127, u = idx & 7;
            const __nv_bfloat16* src = (t == 0) ? ah : (t == 1) ? al : (t == 2) ? bh : bl;
            int grow = ((t < 2) ? bm : bn) + r;
            uint4 v = *(const uint4*)(src + (size_t)grow * 512 + kc * 64 + u * 8);
            *(uint4*)(sm + 1024 + buf * 65536 + t * 16384 + SWZ(r * 128 + u * 16)) = v;
        }
    };

    stage(0, 0); FPROXY(); __syncthreads();
    int cnt0 = 0, cnt1 = 0;
    for (int kc = 0; kc < 8; kc++) {
        int buf = kc & 1;
        if (wid == 0) {
            if (elect1()) {
                uint32_t ab = sb + 1024 + buf * 65536;
                uint64_t dah = dk(ab), dal = dk(ab + 16384);
                uint64_t dbh = dk(ab + 32768), dbl = dk(ab + 49152);
#pragma unroll
                for (int s = 0; s < 4; s++) mma16(tm, dah + 2*s, dbh + 2*s, ID_128, (kc > 0) || (s > 0));
#pragma unroll
                for (int s = 0; s < 4; s++) mma16(tm, dah + 2*s, dbl + 2*s, ID_128, 1);
#pragma unroll
                for (int s = 0; s < 4; s++) mma16(tm, dal + 2*s, dbh + 2*s, ID_128, 1);
                TC_COMMIT(sb + 8 + buf * 8);
            }
        }
        if (kc < 7) {
            if (kc >= 1) {
                int ob = buf ^ 1;
                int ph = (ob ? cnt1++ : cnt0++) & 1;
                MBAR_WAIT(sb + 8 + ob * 8, ph);
            }
            stage(kc + 1, buf ^ 1); FPROXY(); __syncthreads();
        }
    }
    MBAR_WAIT(sb + 16, cnt1 & 1);
    TC_FA();

    const int r = (wid & 3) * 32 + lane, cb = (wid >> 2) * 64;
    uint32_t u[64];
    LDTM32(u, tm + cb);
    LDTM32(u + 32, tm + cb + 32);
    TC_WLD(); TC_FB();
    float f[64];
#pragma unroll
    for (int j = 0; j < 64; j++)
        f[j] = scale * (__uint_as_float(u[j]) + bias[bn + cb + j]);
    float* p = of + (size_t)(bm + r) * 512 + bn + cb;
#pragma unroll
    for (int g = 0; g < 16; g++)
        *(float4*)(p + g * 4) = make_float4(f[g*4], f[g*4+1], f[g*4+2], f[g*4+3]);
    __syncthreads();
    if (wid == 0) TC_DEALLOC(tm, 128);
}

// ------------------------- SIMT flash attention (R1, known correct) --------
#define SPAD 68
#define ATTN_SMEM (4 * 64 * SPAD * 4)

__global__ __launch_bounds__(256) void attn64(
    const float* __restrict__ gq, const float* __restrict__ gk,
    const float* __restrict__ gv, float* __restrict__ go)
{
    extern __shared__ float smf[];
    float (*Qts)[SPAD] = (float(*)[SPAD])(smf);
    float (*Kts)[SPAD] = (float(*)[SPAD])(smf + 64 * SPAD);
    float (*Vs)[SPAD]  = (float(*)[SPAD])(smf + 2 * 64 * SPAD);
    float (*Pts)[SPAD] = (float(*)[SPAD])(smf + 3 * 64 * SPAD);

    const int tid = threadIdx.x;
    const int ty = tid >> 4, tx = tid & 15;
    const int qt0 = blockIdx.x * 64, h = blockIdx.y, b = blockIdx.z;
    const int lr = tid >> 2, lc = (tid & 3) * 4;

    {
        const float* qp = gq + ((size_t)(b * 2048 + qt0 + lr)) * 512 + h * 64;
#pragma unroll
        for (int q4 = 0; q4 < 4; q4++) {
            int d = lc + q4 * 16;
            float4 v = *(const float4*)(qp + d);
            Qts[d + 0][lr] = v.x; Qts[d + 1][lr] = v.y;
            Qts[d + 2][lr] = v.z; Qts[d + 3][lr] = v.w;
        }
    }

    float oacc[16];
#pragma unroll
    for (int i = 0; i < 16; i++) oacc[i] = 0.0f;

    for (int src = 0; src < NSRC; src++) {
        const float* K = gk + ((size_t)(src * 2 + b)) * 2048 * 512 + h * 64;
        const float* V = gv + ((size_t)(src * 2 + b)) * 2048 * 512 + h * 64;
        float o[16];
#pragma unroll
        for (int i = 0; i < 16; i++) o[i] = 0.0f;
        float mrow[4] = {-1e30f, -1e30f, -1e30f, -1e30f};
        float lrow[4] = {0.0f, 0.0f, 0.0f, 0.0f};

        for (int kt = 0; kt < 32; kt++) {
            __syncthreads();
            {
                const float* kp = K + (size_t)(kt * 64 + lr) * 512;
                const float* vp = V + (size_t)(kt * 64 + lr) * 512;
#pragma unroll
                for (int q4 = 0; q4 < 4; q4++) {
                    int d = lc + q4 * 16;
                    float4 kv = *(const float4*)(kp + d);
                    Kts[d + 0][lr] = kv.x; Kts[d + 1][lr] = kv.y;
                    Kts[d + 2][lr] = kv.z; Kts[d + 3][lr] = kv.w;
                    float4 vv = *(const float4*)(vp + d);
                    *(float4*)&Vs[lr][d] = vv;
                }
            }
            __syncthreads();

            float s[4][4];
#pragma unroll
            for (int j = 0; j < 4; j++)
#pragma unroll
                for (int jj = 0; jj < 4; jj++) s[j][jj] = 0.0f;
#pragma unroll
            for (int k = 0; k < 64; k++) {
                float4 a  = *(const float4*)&Qts[k][ty * 4];
                float4 bb = *(const float4*)&Kts[k][tx * 4];
                s[0][0] += a.x * bb.x; s[0][1] += a.x * bb.y; s[0][2] += a.x * bb.z; s[0][3] += a.x * bb.w;
                s[1][0] += a.y * bb.x; s[1][1] += a.y * bb.y; s[1][2] += a.y * bb.z; s[1][3] += a.y * bb.w;
                s[2][0] += a.z * bb.x; s[2][1] += a.z * bb.y; s[2][2] += a.z * bb.z; s[2][3] += a.z * bb.w;
                s[3][0] += a.w * bb.x; s[3][1] += a.w * bb.y; s[3][2] += a.w * bb.z; s[3][3] += a.w * bb.w;
            }

#pragma unroll
            for (int j = 0; j < 4; j++) {
                float mt = fmaxf(fmaxf(s[j][0], s[j][1]), fmaxf(s[j][2], s[j][3]));
#pragma unroll
                for (int w = 1; w < 16; w <<= 1)
                    mt = fmaxf(mt, __shfl_xor_sync(0xffffffffu, mt, w));
                float mnew = fmaxf(mrow[j], mt);
                float corr = __expf(mrow[j] - mnew);
                mrow[j] = mnew;
                lrow[j] *= corr;
                o[j*4+0] *= corr; o[j*4+1] *= corr; o[j*4+2] *= corr; o[j*4+3] *= corr;
                float ps = 0.0f;
#pragma unroll
                for (int jj = 0; jj < 4; jj++) {
                    float p = __expf(s[j][jj] - mnew);
                    ps += p;
                    Pts[tx * 4 + jj][ty * 4 + j] = p;
                }
#pragma unroll
                for (int w = 1; w < 16; w <<= 1)
                    ps += __shfl_xor_sync(0xffffffffu, ps, w);
                lrow[j] += ps;
            }
            __syncthreads();

#pragma unroll
            for (int c = 0; c < 64; c++) {
                float4 p = *(const float4*)&Pts[c][ty * 4];
                float4 v = *(const float4*)&Vs[c][tx * 4];
                o[0]  += p.x * v.x; o[1]  += p.x * v.y; o[2]  += p.x * v.z; o[3]  += p.x * v.w;
                o[4]  += p.y * v.x; o[5]  += p.y * v.y; o[6]  += p.y * v.z; o[7]  += p.y * v.w;
                o[8]  += p.z * v.x; o[9]  += p.z * v.y; o[10] += p.z * v.z; o[11] += p.z * v.w;
                o[12] += p.w * v.x; o[13] += p.w * v.y; o[14] += p.w * v.z; o[15] += p.w * v.w;
            }
        }
#pragma unroll
        for (int j = 0; j < 4; j++) {
            float inv = 1.0f / lrow[j];
#pragma unroll
            for (int jj = 0; jj < 4; jj++)
                oacc[j * 4 + jj] += o[j * 4 + jj] * inv;
        }
    }
#pragma unroll
    for (int j = 0; j < 4; j++) {
        float4 w4 = make_float4(oacc[j*4+0], oacc[j*4+1], oacc[j*4+2], oacc[j*4+3]);
        *(float4*)(go + ((size_t)(b * 2048 + qt0 + ty * 4 + j)) * 512 + h * 64 + tx * 4) = w4;
    }
}

// ---------------------------------------------------------------------------
extern "C" void kernel_launch(void* const* d_in, const int* in_sizes, int n_in,
                              void* d_out, int out_size)
{
    const float* x  = (const float*)d_in[0];
    const float* y  = (const float*)d_in[1];
    const float* Wq = (const float*)d_in[2];
    const float* bq = (const float*)d_in[3];
    const float* Wk = (const float*)d_in[4];
    const float* bk = (const float*)d_in[5];
    const float* Wv = (const float*)d_in[6];
    const float* bv = (const float*)d_in[7];
    const float* Wp = (const float*)d_in[8];
    const float* bp = (const float*)d_in[9];
    float* out = (float*)d_out;

    __nv_bfloat16 *xh, *xl, *yh, *yl, *wh, *wl, *Oh, *Ol;
    float *pq, *pk, *pv, *po;
    cudaGetSymbolAddress((void**)&xh, g_xh); cudaGetSymbolAddress((void**)&xl, g_xl);
    cudaGetSymbolAddress((void**)&yh, g_yh); cudaGetSymbolAddress((void**)&yl, g_yl);
    cudaGetSymbolAddress((void**)&wh, g_wh); cudaGetSymbolAddress((void**)&wl, g_wl);
    cudaGetSymbolAddress((void**)&pq, g_q);  cudaGetSymbolAddress((void**)&pk, g_k);
    cudaGetSymbolAddress((void**)&pv, g_v);  cudaGetSymbolAddress((void**)&po, g_o);
    cudaGetSymbolAddress((void**)&Oh, g_oh); cudaGetSymbolAddress((void**)&Ol, g_ol);

    const int GSM = 1024 + 2 * 4 * 16384;   // 132 KB
    cudaFuncSetAttribute(tgemm,  cudaFuncAttributeMaxDynamicSharedMemorySize, GSM);
    cudaFuncSetAttribute(attn64, cudaFuncAttributeMaxDynamicSharedMemorySize, ATTN_SMEM);

    splitk<<<512, 256>>>(x, xh, xl, ELEM_X / 4);
    splitk<<<1024, 256>>>(y, yh, yl, ELEM_Y / 4);
    wtsk<<<dim3(16, 16, 1), dim3(32, 32)>>>(Wq, wh,            wl);
    wtsk<<<dim3(16, 16, 3), dim3(32, 32)>>>(Wk, wh + 1 * WSTR, wl + 1 * WSTR);
    wtsk<<<dim3(16, 16, 3), dim3(32, 32)>>>(Wv, wh + 4 * WSTR, wl + 4 * WSTR);
    wtsk<<<dim3(16, 16, 1), dim3(32, 32)>>>(Wp, wh + 7 * WSTR, wl + 7 * WSTR);

    dim3 gg(4, 32), gb(256);
    tgemm<<<gg, gb, GSM>>>(xh, xl, wh, wl, bq, pq, 0.125f);
    for (int i = 0; i < NSRC; i++) {
        size_t off = (size_t)i * 2 * 2048 * 512;
        tgemm<<<gg, gb, GSM>>>(yh + off, yl + off, wh + (1 + i) * WSTR, wl + (1 + i) * WSTR,
                               bk + i * 512, pk + off, 1.0f);
        tgemm<<<gg, gb, GSM>>>(yh + off, yl + off, wh + (4 + i) * WSTR, wl + (4 + i) * WSTR,
                               bv + i * 512, pv + off, 1.0f);
    }
    attn64<<<dim3(32, 8, 2), gb, ATTN_SMEM>>>(pq, pk, pv, po);
    splitk<<<512, 256>>>(po, Oh, Ol, ELEM_X / 4);
    tgemm<<<gg, gb, GSM>>>(Oh, Ol, wh + 7 * WSTR, wl + 7 * WSTR, bp, out, 1.0f);
}

// round 7
// speedup vs baseline: 5.0237x; 4.1213x over previous
#include <cuda_runtime.h>
#include <cuda_bf16.h>
#include <stdint.h>

#define NSRC 3
#define ELEM_X (2*2048*512)
#define ELEM_Y (3*2*2048*512)
#define WSTR   (512*512)

__device__ __nv_bfloat16 g_xh[ELEM_X], g_xl[ELEM_X];
__device__ __nv_bfloat16 g_yh[ELEM_Y], g_yl[ELEM_Y];
__device__ __nv_bfloat16 g_wh[8*WSTR], g_wl[8*WSTR];
__device__ __nv_bfloat16 g_qh[ELEM_X], g_ql[ELEM_X];
__device__ __nv_bfloat16 g_kh[ELEM_Y], g_kl[ELEM_Y];
__device__ __nv_bfloat16 g_vth[ELEM_Y], g_vtl[ELEM_Y];   // V^T: [src*512+n][4096]
__device__ __nv_bfloat16 g_oh[ELEM_X], g_ol[ELEM_X];

#define SWZ(o) ((uint32_t)(o) ^ ((((uint32_t)(o)) >> 3) & 0x70u))
#define ID_128 0x8200490u   /* kind::f16 f32acc bf16 M=128 N=128 K-major/K-major */
#define ID_PV  0x8100490u   /* kind::f16 f32acc bf16 M=128 N=64  K-major/K-major */

#if defined(__CUDA_ARCH_FEAT_SM103_ALL) || defined(__CUDA_ARCH_FEAT_SM100_ALL) || !defined(__CUDA_ARCH__)
#define HAS_TC5 1
#else
#define HAS_TC5 0
#endif

__device__ __forceinline__ uint32_t elect1() {
    uint32_t p;
    asm volatile("{\n\t.reg .pred p;\n\telect.sync _|p, 0xFFFFFFFF;\n\tselp.b32 %0,1,0,p;\n\t}" : "=r"(p));
    return p;
}
__device__ __forceinline__ uint32_t s2u(const void* p) {
    uint32_t a;
    asm("{ .reg .u64 t; cvta.to.shared.u64 t, %1; cvt.u32.u64 %0, t; }" : "=r"(a) : "l"(p));
    return a;
}
__device__ __forceinline__ uint64_t dk(uint32_t a) {   // K-major SW128 desc
    return (2ull<<61)|(1ull<<46)|(64ull<<32)|(1ull<<16)|((uint64_t)(a>>4)&0x3FFFull);
}

#define MBAR_INIT(a,n) asm volatile("mbarrier.init.shared.b64 [%0], %1;" :: "r"(a), "r"(n) : "memory")
#define MBAR_WAIT(a,ph) asm volatile("{\n\t.reg .pred P1;\n\tLW%=:\n\t" \
    "mbarrier.try_wait.parity.acquire.cta.shared::cta.b64 P1, [%0], %1, 0x989680;\n\t" \
    "@P1 bra.uni LD%=;\n\tbra.uni LW%=;\n\tLD%=:\n\t}" :: "r"(a), "r"(ph) : "memory")
#define FPROXY()       asm volatile("fence.proxy.async.shared::cta;" ::: "memory")

#if HAS_TC5
__device__ __forceinline__ void mma16(uint32_t d, uint64_t a, uint64_t b, uint32_t id, uint32_t acc) {
    asm volatile("{\n\t.reg .pred p;\n\tsetp.ne.u32 p, %4, 0;\n\t"
        "tcgen05.mma.cta_group::1.kind::f16 [%0], %1, %2, %3, {%5,%5,%5,%5}, p;\n\t}"
        :: "r"(d), "l"(a), "l"(b), "r"(id), "r"(acc), "r"(0u) : "memory");
}
#define TC_ALLOC(a,n)  asm volatile("tcgen05.alloc.cta_group::1.sync.aligned.shared::cta.b32 [%0], %1;" :: "r"(a), "r"(n) : "memory")
#define TC_RELQ()      asm volatile("tcgen05.relinquish_alloc_permit.cta_group::1.sync.aligned;")
#define TC_DEALLOC(t,n) asm volatile("tcgen05.dealloc.cta_group::1.sync.aligned.b32 %0, %1;" :: "r"(t), "r"(n))
#define TC_COMMIT(a)   asm volatile("tcgen05.commit.cta_group::1.mbarrier::arrive::one.shared::cluster.b64 [%0];" :: "r"(a) : "memory")
#define TC_FA()        asm volatile("tcgen05.fence::after_thread_sync;" ::: "memory")
#define TC_FB()        asm volatile("tcgen05.fence::before_thread_sync;" ::: "memory")
#define TC_WLD()       asm volatile("tcgen05.wait::ld.sync.aligned;" ::: "memory")
#define LDTM32(r, a) asm volatile( \
    "tcgen05.ld.sync.aligned.32x32b.x32.b32 " \
    "{%0,%1,%2,%3,%4,%5,%6,%7,%8,%9,%10,%11,%12,%13,%14,%15," \
    "%16,%17,%18,%19,%20,%21,%22,%23,%24,%25,%26,%27,%28,%29,%30,%31}, [%32];" \
    : "=r"((r)[0]),"=r"((r)[1]),"=r"((r)[2]),"=r"((r)[3]),"=r"((r)[4]),"=r"((r)[5]),"=r"((r)[6]),"=r"((r)[7]), \
      "=r"((r)[8]),"=r"((r)[9]),"=r"((r)[10]),"=r"((r)[11]),"=r"((r)[12]),"=r"((r)[13]),"=r"((r)[14]),"=r"((r)[15]), \
      "=r"((r)[16]),"=r"((r)[17]),"=r"((r)[18]),"=r"((r)[19]),"=r"((r)[20]),"=r"((r)[21]),"=r"((r)[22]),"=r"((r)[23]), \
      "=r"((r)[24]),"=r"((r)[25]),"=r"((r)[26]),"=r"((r)[27]),"=r"((r)[28]),"=r"((r)[29]),"=r"((r)[30]),"=r"((r)[31]) \
    : "r"(a))
#else
__device__ __forceinline__ void mma16(uint32_t, uint64_t, uint64_t, uint32_t, uint32_t) { __trap(); }
#define TC_ALLOC(a,n)   __trap()
#define TC_RELQ()       __trap()
#define TC_DEALLOC(t,n) __trap()
#define TC_COMMIT(a)    __trap()
#define TC_FA()         ((void)0)
#define TC_FB()         ((void)0)
#define TC_WLD()        ((void)0)
#define LDTM32(r, a) do { _Pragma("unroll") for (int _i = 0; _i < 32; _i++) (r)[_i] = 0u; __trap(); } while (0)
#endif

__device__ __forceinline__ uint32_t packh(__nv_bfloat16 a, __nv_bfloat16 b) {
    __nv_bfloat162 v; v.x = a; v.y = b;
    return *reinterpret_cast<uint32_t*>(&v);
}

// ------------------------- prep kernels -----------------------------------
__global__ void splitk(const float* __restrict__ in, __nv_bfloat16* __restrict__ oh,
                       __nv_bfloat16* __restrict__ ol, int n4) {
    for (int i = blockIdx.x * blockDim.x + threadIdx.x; i < n4; i += gridDim.x * blockDim.x) {
        float4 v = ((const float4*)in)[i];
        __nv_bfloat16 h0 = __float2bfloat16_rn(v.x), h1 = __float2bfloat16_rn(v.y);
        __nv_bfloat16 h2 = __float2bfloat16_rn(v.z), h3 = __float2bfloat16_rn(v.w);
        __nv_bfloat16 l0 = __float2bfloat16_rn(v.x - __bfloat162float(h0));
        __nv_bfloat16 l1 = __float2bfloat16_rn(v.y - __bfloat162float(h1));
        __nv_bfloat16 l2 = __float2bfloat16_rn(v.z - __bfloat162float(h2));
        __nv_bfloat16 l3 = __float2bfloat16_rn(v.w - __bfloat162float(h3));
        *(uint2*)(oh + 4 * (size_t)i) = make_uint2(packh(h0, h1), packh(h2, h3));
        *(uint2*)(ol + 4 * (size_t)i) = make_uint2(packh(l0, l1), packh(l2, l3));
    }
}

__global__ void wtsk(const float* __restrict__ W, __nv_bfloat16* __restrict__ th,
                     __nv_bfloat16* __restrict__ tl) {
    __shared__ float t[32][33];
    int m = blockIdx.z;
    int k0 = blockIdx.x * 32, n0 = blockIdx.y * 32;
    const float* Wm = W + (size_t)m * WSTR;
    t[threadIdx.y][threadIdx.x] = Wm[(size_t)(k0 + threadIdx.y) * 512 + n0 + threadIdx.x];
    __syncthreads();
    float v = t[threadIdx.x][threadIdx.y];
    size_t di = (size_t)m * WSTR + (size_t)(n0 + threadIdx.y) * 512 + k0 + threadIdx.x;
    __nv_bfloat16 h = __float2bfloat16_rn(v);
    th[di] = h;
    tl[di] = __float2bfloat16_rn(v - __bfloat162float(h));
}

// ------------------------- tcgen05 GEMM -----------------------------------
// MODE 0: fp32 out [m][n].  MODE 1: split bf16 out [m][n].
// MODE 2: split bf16 TRANSPOSED out [n][4096 m]  (for V^T).
template <int MODE>
__global__ __launch_bounds__(256) void tgemm(
    const __nv_bfloat16* __restrict__ ah, const __nv_bfloat16* __restrict__ al,
    const __nv_bfloat16* __restrict__ bh, const __nv_bfloat16* __restrict__ bl,
    const float* __restrict__ bias, float* __restrict__ of,
    __nv_bfloat16* __restrict__ oh, __nv_bfloat16* __restrict__ ol, float scale)
{
    extern __shared__ char sm[];
    const uint32_t sb = s2u(sm);
    const int tid = threadIdx.x, wid = tid >> 5, lane = tid & 31;
    const int bm = blockIdx.y * 128, bn = blockIdx.x * 128;

    if (wid == 0) { TC_ALLOC(sb, 128); TC_RELQ(); }
    if (tid == 0) { MBAR_INIT(sb + 8, 1); MBAR_INIT(sb + 16, 1); }
    __syncthreads();
    uint32_t tm;
    asm volatile("ld.shared.b32 %0, [%1];" : "=r"(tm) : "r"(sb));

    auto stage = [&](int kc, int buf) {
#pragma unroll
        for (int i = 0; i < 16; i++) {
            int idx = tid + i * 256;
            int t = idx >> 10, r = (idx >> 3) & 127, u = idx & 7;
            const __nv_bfloat16* src = (t == 0) ? ah : (t == 1) ? al : (t == 2) ? bh : bl;
            int grow = ((t < 2) ? bm : bn) + r;
            uint4 v = *(const uint4*)(src + (size_t)grow * 512 + kc * 64 + u * 8);
            *(uint4*)(sm + 1024 + buf * 65536 + t * 16384 + SWZ(r * 128 + u * 16)) = v;
        }
    };

    stage(0, 0); FPROXY(); __syncthreads();
    int cnt0 = 0, cnt1 = 0;
    for (int kc = 0; kc < 8; kc++) {
        int buf = kc & 1;
        if (wid == 0) {
            if (elect1()) {
                uint32_t ab = sb + 1024 + buf * 65536;
                uint64_t dah = dk(ab), dal = dk(ab + 16384);
                uint64_t dbh = dk(ab + 32768), dbl = dk(ab + 49152);
#pragma unroll
                for (int s = 0; s < 4; s++) mma16(tm, dah + 2*s, dbh + 2*s, ID_128, (kc > 0) || (s > 0));
#pragma unroll
                for (int s = 0; s < 4; s++) mma16(tm, dah + 2*s, dbl + 2*s, ID_128, 1);
#pragma unroll
                for (int s = 0; s < 4; s++) mma16(tm, dal + 2*s, dbh + 2*s, ID_128, 1);
                TC_COMMIT(sb + 8 + buf * 8);
            }
        }
        if (kc < 7) {
            if (kc >= 1) {
                int ob = buf ^ 1;
                int ph = (ob ? cnt1++ : cnt0++) & 1;
                MBAR_WAIT(sb + 8 + ob * 8, ph);
            }
            stage(kc + 1, buf ^ 1); FPROXY(); __syncthreads();
        }
    }
    MBAR_WAIT(sb + 16, cnt1 & 1);
    TC_FA();

    const int r = (wid & 3) * 32 + lane, cb = (wid >> 2) * 64;
    uint32_t u[64];
    LDTM32(u, tm + cb);
    LDTM32(u + 32, tm + cb + 32);
    TC_WLD(); TC_FB();
    float f[64];
#pragma unroll
    for (int j = 0; j < 64; j++)
        f[j] = scale * (__uint_as_float(u[j]) + bias[bn + cb + j]);
    if (MODE == 0) {
        float* p = of + (size_t)(bm + r) * 512 + bn + cb;
#pragma unroll
        for (int g = 0; g < 16; g++)
            *(float4*)(p + g * 4) = make_float4(f[g*4], f[g*4+1], f[g*4+2], f[g*4+3]);
    } else if (MODE == 1) {
        uint32_t hw[32], lw[32];
#pragma unroll
        for (int j = 0; j < 32; j++) {
            __nv_bfloat16 h0 = __float2bfloat16_rn(f[2*j]), h1 = __float2bfloat16_rn(f[2*j+1]);
            hw[j] = packh(h0, h1);
            lw[j] = packh(__float2bfloat16_rn(f[2*j]   - __bfloat162float(h0)),
                          __float2bfloat16_rn(f[2*j+1] - __bfloat162float(h1)));
        }
        size_t o = (size_t)(bm + r) * 512 + bn + cb;
#pragma unroll
        for (int g = 0; g < 8; g++) {
            *(uint4*)(oh + o + g * 8) = make_uint4(hw[g*4], hw[g*4+1], hw[g*4+2], hw[g*4+3]);
            *(uint4*)(ol + o + g * 8) = make_uint4(lw[g*4], lw[g*4+1], lw[g*4+2], lw[g*4+3]);
        }
    } else {
        // transposed split: out[n][4096 m]
#pragma unroll
        for (int j = 0; j < 64; j++) {
            __nv_bfloat16 h0 = __float2bfloat16_rn(f[j]);
            __nv_bfloat16 l0 = __float2bfloat16_rn(f[j] - __bfloat162float(h0));
            size_t o = (size_t)(bn + cb + j) * 4096 + bm + r;
            oh[o] = h0;
            ol[o] = l0;
        }
    }
    __syncthreads();
    if (wid == 0) TC_DEALLOC(tm, 128);
}

// ------------------------- fused tcgen05 attention -------------------------
// CTA = (128-q tile, head, batch). S = QK^T (verified K-major SS path).
// PV: A = P (blocked K-major, 2 atom cols), B = V^T tile (64 d x 128 kv,
// blocked K-major, 2 atom cols) -- no TransB anywhere.
#define A_QH 1024
#define A_QL (A_QH + 16384)
#define A_KH (A_QL + 16384)
#define A_KL (A_KH + 16384)
#define A_VH (A_KL + 16384)
#define A_VL (A_VH + 16384)
#define A_PH (A_VL + 16384)
#define A_PL (A_PH + 32768)
#define A_SMEM (A_PL + 32768)

__global__ __launch_bounds__(256) void attn(
    const __nv_bfloat16* __restrict__ qh, const __nv_bfloat16* __restrict__ ql,
    const __nv_bfloat16* __restrict__ kh, const __nv_bfloat16* __restrict__ kl,
    const __nv_bfloat16* __restrict__ vth, const __nv_bfloat16* __restrict__ vtl,
    __nv_bfloat16* __restrict__ oh, __nv_bfloat16* __restrict__ ol)
{
    extern __shared__ char sm[];
    const uint32_t sb = s2u(sm);
    float* lsum = (float*)(sm + 32);
    const int tid = threadIdx.x, wid = tid >> 5, lane = tid & 31;
    const int q0 = blockIdx.x * 128, h = blockIdx.y, b = blockIdx.z;

    if (wid == 0) { TC_ALLOC(sb, 256); TC_RELQ(); }
    if (tid == 0) { MBAR_INIT(sb + 8, 1); MBAR_INIT(sb + 16, 1); }
    __syncthreads();
    uint32_t tm;
    asm volatile("ld.shared.b32 %0, [%1];" : "=r"(tm) : "r"(sb));
    const uint32_t tms = tm, tmo = tm + 128;

    // Q tile hi/lo (once): [128 q][64 d], K-major rows of 128B
#pragma unroll
    for (int i = 0; i < 8; i++) {
        int idx = tid + i * 256;
        int t = idx >> 10, r = (idx >> 3) & 127, u = idx & 7;
        const __nv_bfloat16* src = t ? ql : qh;
        uint4 v = *(const uint4*)(src + (size_t)(b * 2048 + q0 + r) * 512 + h * 64 + u * 8);
        *(uint4*)(sm + A_QH + t * 16384 + SWZ(r * 128 + u * 16)) = v;
    }
    FPROXY(); __syncthreads();

    const int r = (wid & 3) * 32 + lane;
    const int cb = (wid >> 2) * 64;    // S cols
    const int cb2 = (wid >> 2) * 32;   // O cols
    float oacc[32];
#pragma unroll
    for (int j = 0; j < 32; j++) oacc[j] = 0.0f;

    int scnt = 0, pvcnt = 0;
    for (int src = 0; src < 3; src++) {
        if (tid < 128) lsum[tid] = 0.0f;
        const size_t kvb = ((size_t)(src * 2 + b)) * 2048 * 512 + h * 64;
        const size_t vtb = ((size_t)(src * 512 + h * 64)) * 4096 + b * 2048;

        for (int kt = 0; kt < 16; kt++) {
            if (kt > 0) { MBAR_WAIT(sb + 16, pvcnt & 1); pvcnt++; }
            // stage K hi/lo (128 kv x 64 d) and V^T hi/lo (64 d x 128 kv, blocked)
#pragma unroll
            for (int i = 0; i < 16; i++) {
                int idx = tid + i * 256;
                int mat = idx >> 10, rem = idx & 1023;
                if (mat < 2) {
                    int rr = rem >> 3, u = rem & 7;
                    const __nv_bfloat16* s0 = mat ? kl : kh;
                    uint4 v = *(const uint4*)(s0 + kvb + (size_t)(kt * 128 + rr) * 512 + u * 8);
                    *(uint4*)(sm + A_KH + mat * 16384 + SWZ(rr * 128 + u * 16)) = v;
                } else {
                    int d = rem >> 4, u = rem & 15;
                    const __nv_bfloat16* s0 = (mat == 2) ? vth : vtl;
                    uint4 v = *(const uint4*)(s0 + vtb + (size_t)d * 4096 + kt * 128 + u * 8);
                    *(uint4*)(sm + A_VH + (mat - 2) * 16384 + (u >> 3) * 8192 +
                              SWZ(d * 128 + (u & 7) * 16)) = v;
                }
            }
            FPROXY(); __syncthreads();

            // S = Q K^T (3 split MMAs, K=64)
            if (wid == 0) {
                if (elect1()) {
                    uint64_t dqh = dk(sb + A_QH), dql = dk(sb + A_QL);
                    uint64_t dkh = dk(sb + A_KH), dkl = dk(sb + A_KL);
#pragma unroll
                    for (int s = 0; s < 4; s++) mma16(tms, dqh + 2*s, dkh + 2*s, ID_128, s > 0);
#pragma unroll
                    for (int s = 0; s < 4; s++) mma16(tms, dqh + 2*s, dkl + 2*s, ID_128, 1);
#pragma unroll
                    for (int s = 0; s < 4; s++) mma16(tms, dql + 2*s, dkh + 2*s, ID_128, 1);
                    TC_COMMIT(sb + 8);
                }
            }
            MBAR_WAIT(sb + 8, scnt & 1); scnt++;
            TC_FA();

            // softmax (no max; logits O(1)): exp, row-sum, split P to smem
            uint32_t u0[64];
            LDTM32(u0, tms + cb);
            LDTM32(u0 + 32, tms + cb + 32);
            TC_WLD(); TC_FB();
            float ps = 0.0f;
#pragma unroll
            for (int j4 = 0; j4 < 16; j4++) {
                uint32_t hw[2], lw[2];
#pragma unroll
                for (int p = 0; p < 2; p++) {
                    float e0 = __expf(fminf(__uint_as_float(u0[j4*4 + p*2]),     60.f));
                    float e1 = __expf(fminf(__uint_as_float(u0[j4*4 + p*2 + 1]), 60.f));
                    ps += e0 + e1;
                    __nv_bfloat16 h0 = __float2bfloat16_rn(e0), h1 = __float2bfloat16_rn(e1);
                    hw[p] = packh(h0, h1);
                    lw[p] = packh(__float2bfloat16_rn(e0 - __bfloat162float(h0)),
                                  __float2bfloat16_rn(e1 - __bfloat162float(h1)));
                }
                int t = cb + j4 * 4;
                uint32_t off = (uint32_t)((t >> 6) * 16384) + SWZ(r * 128 + (t & 63) * 2);
                *(uint2*)(sm + A_PH + off) = make_uint2(hw[0], hw[1]);
                *(uint2*)(sm + A_PL + off) = make_uint2(lw[0], lw[1]);
            }
            atomicAdd(&lsum[r], ps);
            FPROXY(); __syncthreads();

            // O += P V : blocked K-major A (P) x blocked K-major B (V^T)
            if (wid == 0) {
                if (elect1()) {
                    uint64_t dph = dk(sb + A_PH), dpl = dk(sb + A_PL);
                    uint64_t dvh = dk(sb + A_VH), dvl = dk(sb + A_VL);
#pragma unroll
                    for (int s = 0; s < 8; s++) {
                        uint64_t pa = (uint64_t)((s >> 2) * 1024 + (s & 3) * 2);
                        uint64_t vb = (uint64_t)((s >> 2) * 512  + (s & 3) * 2);
                        mma16(tmo, dph + pa, dvh + vb, ID_PV, (kt > 0) || (s > 0));
                    }
#pragma unroll
                    for (int s = 0; s < 8; s++) {
                        uint64_t pa = (uint64_t)((s >> 2) * 1024 + (s & 3) * 2);
                        uint64_t vb = (uint64_t)((s >> 2) * 512  + (s & 3) * 2);
                        mma16(tmo, dph + pa, dvl + vb, ID_PV, 1);
                    }
#pragma unroll
                    for (int s = 0; s < 8; s++) {
                        uint64_t pa = (uint64_t)((s >> 2) * 1024 + (s & 3) * 2);
                        uint64_t vb = (uint64_t)((s >> 2) * 512  + (s & 3) * 2);
                        mma16(tmo, dpl + pa, dvh + vb, ID_PV, 1);
                    }
                    TC_COMMIT(sb + 16);
                }
            }
        }
        MBAR_WAIT(sb + 16, pvcnt & 1); pvcnt++;
        TC_FA();
        __syncthreads();     // lsum atomics done

        uint32_t uo[32];
        LDTM32(uo, tmo + cb2);
        TC_WLD(); TC_FB();
        float inv = 1.0f / lsum[r];
#pragma unroll
        for (int j = 0; j < 32; j++) oacc[j] += __uint_as_float(uo[j]) * inv;
        __syncthreads();     // before lsum reset / O overwrite
    }

    // write O split hi/lo
    uint32_t hw[16], lw[16];
#pragma unroll
    for (int j = 0; j < 16; j++) {
        __nv_bfloat16 h0 = __float2bfloat16_rn(oacc[2*j]), h1 = __float2bfloat16_rn(oacc[2*j+1]);
        hw[j] = packh(h0, h1);
        lw[j] = packh(__float2bfloat16_rn(oacc[2*j]   - __bfloat162float(h0)),
                      __float2bfloat16_rn(oacc[2*j+1] - __bfloat162float(h1)));
    }
    size_t o = (size_t)(b * 2048 + q0 + r) * 512 + h * 64 + cb2;
#pragma unroll
    for (int g = 0; g < 4; g++) {
        *(uint4*)(oh + o + g * 8) = make_uint4(hw[g*4], hw[g*4+1], hw[g*4+2], hw[g*4+3]);
        *(uint4*)(ol + o + g * 8) = make_uint4(lw[g*4], lw[g*4+1], lw[g*4+2], lw[g*4+3]);
    }
    __syncthreads();
    if (wid == 0) TC_DEALLOC(tm, 256);
}

// ---------------------------------------------------------------------------
extern "C" void kernel_launch(void* const* d_in, const int* in_sizes, int n_in,
                              void* d_out, int out_size)
{
    const float* x  = (const float*)d_in[0];
    const float* y  = (const float*)d_in[1];
    const float* Wq = (const float*)d_in[2];
    const float* bq = (const float*)d_in[3];
    const float* Wk = (const float*)d_in[4];
    const float* bk = (const float*)d_in[5];
    const float* Wv = (const float*)d_in[6];
    const float* bv = (const float*)d_in[7];
    const float* Wp = (const float*)d_in[8];
    const float* bp = (const float*)d_in[9];
    float* out = (float*)d_out;

    __nv_bfloat16 *xh, *xl, *yh, *yl, *wh, *wl, *Qh, *Ql, *Kh, *Kl, *Vth, *Vtl, *Oh, *Ol;
    cudaGetSymbolAddress((void**)&xh, g_xh);  cudaGetSymbolAddress((void**)&xl, g_xl);
    cudaGetSymbolAddress((void**)&yh, g_yh);  cudaGetSymbolAddress((void**)&yl, g_yl);
    cudaGetSymbolAddress((void**)&wh, g_wh);  cudaGetSymbolAddress((void**)&wl, g_wl);
    cudaGetSymbolAddress((void**)&Qh, g_qh);  cudaGetSymbolAddress((void**)&Ql, g_ql);
    cudaGetSymbolAddress((void**)&Kh, g_kh);  cudaGetSymbolAddress((void**)&Kl, g_kl);
    cudaGetSymbolAddress((void**)&Vth, g_vth); cudaGetSymbolAddress((void**)&Vtl, g_vtl);
    cudaGetSymbolAddress((void**)&Oh, g_oh);  cudaGetSymbolAddress((void**)&Ol, g_ol);

    const int GSM = 1024 + 2 * 4 * 16384;   // 132 KB
    cudaFuncSetAttribute(tgemm<0>, cudaFuncAttributeMaxDynamicSharedMemorySize, GSM);
    cudaFuncSetAttribute(tgemm<1>, cudaFuncAttributeMaxDynamicSharedMemorySize, GSM);
    cudaFuncSetAttribute(tgemm<2>, cudaFuncAttributeMaxDynamicSharedMemorySize, GSM);
    cudaFuncSetAttribute(attn,     cudaFuncAttributeMaxDynamicSharedMemorySize, A_SMEM);

    splitk<<<512, 256>>>(x, xh, xl, ELEM_X / 4);
    splitk<<<1024, 256>>>(y, yh, yl, ELEM_Y / 4);
    wtsk<<<dim3(16, 16, 1), dim3(32, 32)>>>(Wq, wh,            wl);
    wtsk<<<dim3(16, 16, 3), dim3(32, 32)>>>(Wk, wh + 1 * WSTR, wl + 1 * WSTR);
    wtsk<<<dim3(16, 16, 3), dim3(32, 32)>>>(Wv, wh + 4 * WSTR, wl + 4 * WSTR);
    wtsk<<<dim3(16, 16, 1), dim3(32, 32)>>>(Wp, wh + 7 * WSTR, wl + 7 * WSTR);

    dim3 gg(4, 32), gb(256);
    tgemm<1><<<gg, gb, GSM>>>(xh, xl, wh, wl, bq, nullptr, Qh, Ql, 0.125f);
    for (int i = 0; i < NSRC; i++) {
        size_t off = (size_t)i * 2 * 2048 * 512;
        tgemm<1><<<gg, gb, GSM>>>(yh + off, yl + off, wh + (1 + i) * WSTR, wl + (1 + i) * WSTR,
                                  bk + i * 512, nullptr, Kh + off, Kl + off, 1.0f);
        tgemm<2><<<gg, gb, GSM>>>(yh + off, yl + off, wh + (4 + i) * WSTR, wl + (4 + i) * WSTR,
                                  bv + i * 512, nullptr, Vth + off, Vtl + off, 1.0f);
    }
    attn<<<dim3(16, 8, 2), gb, A_SMEM>>>(Qh, Ql, Kh, Kl, Vth, Vtl, Oh, Ol);
    tgemm<0><<<gg, gb, GSM>>>(Oh, Ol, wh + 7 * WSTR, wl + 7 * WSTR, bp, out, nullptr, nullptr, 1.0f);
}

// round 8
// speedup vs baseline: 5.6038x; 1.1155x over previous
#include <cuda_runtime.h>
#include <cuda_bf16.h>
#include <stdint.h>

#define NSRC 3
#define ELEM_X (2*2048*512)
#define ELEM_Y (3*2*2048*512)
#define WSTR   (512*512)

__device__ __nv_bfloat16 g_xh[ELEM_X], g_xl[ELEM_X];
__device__ __nv_bfloat16 g_yh[ELEM_Y], g_yl[ELEM_Y];
__device__ __nv_bfloat16 g_wh[8*WSTR], g_wl[8*WSTR];
__device__ __nv_bfloat16 g_qh[ELEM_X], g_ql[ELEM_X];
__device__ __nv_bfloat16 g_kh[ELEM_Y], g_kl[ELEM_Y];
__device__ __nv_bfloat16 g_vth[ELEM_Y], g_vtl[ELEM_Y];   // V^T: [src*512+n][4096]
__device__ __nv_bfloat16 g_oh[ELEM_X], g_ol[ELEM_X];

#define SWZ(o) ((uint32_t)(o) ^ ((((uint32_t)(o)) >> 3) & 0x70u))
#define ID_128 0x8200490u   /* kind::f16 f32acc bf16 M=128 N=128 */
#define ID_PV  0x8100490u   /* kind::f16 f32acc bf16 M=128 N=64  */

#if defined(__CUDA_ARCH_FEAT_SM103_ALL) || defined(__CUDA_ARCH_FEAT_SM100_ALL) || !defined(__CUDA_ARCH__)
#define HAS_TC5 1
#else
#define HAS_TC5 0
#endif

__device__ __forceinline__ uint32_t elect1() {
    uint32_t p;
    asm volatile("{\n\t.reg .pred p;\n\telect.sync _|p, 0xFFFFFFFF;\n\tselp.b32 %0,1,0,p;\n\t}" : "=r"(p));
    return p;
}
__device__ __forceinline__ uint32_t s2u(const void* p) {
    uint32_t a;
    asm("{ .reg .u64 t; cvta.to.shared.u64 t, %1; cvt.u32.u64 %0, t; }" : "=r"(a) : "l"(p));
    return a;
}
__device__ __forceinline__ uint64_t dk(uint32_t a) {
    return (2ull<<61)|(1ull<<46)|(64ull<<32)|(1ull<<16)|((uint64_t)(a>>4)&0x3FFFull);
}

#define MBAR_INIT(a,n) asm volatile("mbarrier.init.shared.b64 [%0], %1;" :: "r"(a), "r"(n) : "memory")
#define MBAR_WAIT(a,ph) asm volatile("{\n\t.reg .pred P1;\n\tLW%=:\n\t" \
    "mbarrier.try_wait.parity.acquire.cta.shared::cta.b64 P1, [%0], %1, 0x989680;\n\t" \
    "@P1 bra.uni LD%=;\n\tbra.uni LW%=;\n\tLD%=:\n\t}" :: "r"(a), "r"(ph) : "memory")
#define FPROXY()       asm volatile("fence.proxy.async.shared::cta;" ::: "memory")
#define CPA16(d,s)     asm volatile("cp.async.cg.shared.global [%0], [%1], 16;" :: "r"(d), "l"(s))
#define CPA_COMMIT()   asm volatile("cp.async.commit_group;" ::: "memory")
#define CPA_WAIT0()    asm volatile("cp.async.wait_group 0;" ::: "memory")

#if HAS_TC5
__device__ __forceinline__ void mma16(uint32_t d, uint64_t a, uint64_t b, uint32_t id, uint32_t acc) {
    asm volatile("{\n\t.reg .pred p;\n\tsetp.ne.u32 p, %4, 0;\n\t"
        "tcgen05.mma.cta_group::1.kind::f16 [%0], %1, %2, %3, {%5,%5,%5,%5}, p;\n\t}"
        :: "r"(d), "l"(a), "l"(b), "r"(id), "r"(acc), "r"(0u) : "memory");
}
#define TC_ALLOC(a,n)  asm volatile("tcgen05.alloc.cta_group::1.sync.aligned.shared::cta.b32 [%0], %1;" :: "r"(a), "r"(n) : "memory")
#define TC_RELQ()      asm volatile("tcgen05.relinquish_alloc_permit.cta_group::1.sync.aligned;")
#define TC_DEALLOC(t,n) asm volatile("tcgen05.dealloc.cta_group::1.sync.aligned.b32 %0, %1;" :: "r"(t), "r"(n))
#define TC_COMMIT(a)   asm volatile("tcgen05.commit.cta_group::1.mbarrier::arrive::one.shared::cluster.b64 [%0];" :: "r"(a) : "memory")
#define TC_FA()        asm volatile("tcgen05.fence::after_thread_sync;" ::: "memory")
#define TC_FB()        asm volatile("tcgen05.fence::before_thread_sync;" ::: "memory")
#define TC_WLD()       asm volatile("tcgen05.wait::ld.sync.aligned;" ::: "memory")
#define LDTM32(r, a) asm volatile( \
    "tcgen05.ld.sync.aligned.32x32b.x32.b32 " \
    "{%0,%1,%2,%3,%4,%5,%6,%7,%8,%9,%10,%11,%12,%13,%14,%15," \
    "%16,%17,%18,%19,%20,%21,%22,%23,%24,%25,%26,%27,%28,%29,%30,%31}, [%32];" \
    : "=r"((r)[0]),"=r"((r)[1]),"=r"((r)[2]),"=r"((r)[3]),"=r"((r)[4]),"=r"((r)[5]),"=r"((r)[6]),"=r"((r)[7]), \
      "=r"((r)[8]),"=r"((r)[9]),"=r"((r)[10]),"=r"((r)[11]),"=r"((r)[12]),"=r"((r)[13]),"=r"((r)[14]),"=r"((r)[15]), \
      "=r"((r)[16]),"=r"((r)[17]),"=r"((r)[18]),"=r"((r)[19]),"=r"((r)[20]),"=r"((r)[21]),"=r"((r)[22]),"=r"((r)[23]), \
      "=r"((r)[24]),"=r"((r)[25]),"=r"((r)[26]),"=r"((r)[27]),"=r"((r)[28]),"=r"((r)[29]),"=r"((r)[30]),"=r"((r)[31]) \
    : "r"(a))
#else
__device__ __forceinline__ void mma16(uint32_t, uint64_t, uint64_t, uint32_t, uint32_t) { __trap(); }
#define TC_ALLOC(a,n)   __trap()
#define TC_RELQ()       __trap()
#define TC_DEALLOC(t,n) __trap()
#define TC_COMMIT(a)    __trap()
#define TC_FA()         ((void)0)
#define TC_FB()         ((void)0)
#define TC_WLD()        ((void)0)
#define LDTM32(r, a) do { _Pragma("unroll") for (int _i = 0; _i < 32; _i++) (r)[_i] = 0u; __trap(); } while (0)
#endif

__device__ __forceinline__ uint32_t packh(__nv_bfloat16 a, __nv_bfloat16 b) {
    __nv_bfloat162 v; v.x = a; v.y = b;
    return *reinterpret_cast<uint32_t*>(&v);
}
__device__ __forceinline__ uint32_t pack2(float lo, float hi) {
    uint32_t r;
    asm("cvt.rn.bf16x2.f32 %0, %1, %2;" : "=r"(r) : "f"(hi), "f"(lo));
    return r;
}

// ------------------------- prep kernels -----------------------------------
__global__ void splitk(const float* __restrict__ in, __nv_bfloat16* __restrict__ oh,
                       __nv_bfloat16* __restrict__ ol, int n4) {
    for (int i = blockIdx.x * blockDim.x + threadIdx.x; i < n4; i += gridDim.x * blockDim.x) {
        float4 v = ((const float4*)in)[i];
        __nv_bfloat16 h0 = __float2bfloat16_rn(v.x), h1 = __float2bfloat16_rn(v.y);
        __nv_bfloat16 h2 = __float2bfloat16_rn(v.z), h3 = __float2bfloat16_rn(v.w);
        __nv_bfloat16 l0 = __float2bfloat16_rn(v.x - __bfloat162float(h0));
        __nv_bfloat16 l1 = __float2bfloat16_rn(v.y - __bfloat162float(h1));
        __nv_bfloat16 l2 = __float2bfloat16_rn(v.z - __bfloat162float(h2));
        __nv_bfloat16 l3 = __float2bfloat16_rn(v.w - __bfloat162float(h3));
        *(uint2*)(oh + 4 * (size_t)i) = make_uint2(packh(h0, h1), packh(h2, h3));
        *(uint2*)(ol + 4 * (size_t)i) = make_uint2(packh(l0, l1), packh(l2, l3));
    }
}

__global__ void wtsk(const float* __restrict__ W, __nv_bfloat16* __restrict__ th,
                     __nv_bfloat16* __restrict__ tl) {
    __shared__ float t[32][33];
    int m = blockIdx.z;
    int k0 = blockIdx.x * 32, n0 = blockIdx.y * 32;
    const float* Wm = W + (size_t)m * WSTR;
    t[threadIdx.y][threadIdx.x] = Wm[(size_t)(k0 + threadIdx.y) * 512 + n0 + threadIdx.x];
    __syncthreads();
    float v = t[threadIdx.x][threadIdx.y];
    size_t di = (size_t)m * WSTR + (size_t)(n0 + threadIdx.y) * 512 + k0 + threadIdx.x;
    __nv_bfloat16 h = __float2bfloat16_rn(v);
    th[di] = h;
    tl[di] = __float2bfloat16_rn(v - __bfloat162float(h));
}

// ------------------------- tcgen05 GEMM (unchanged, verified) --------------
template <int MODE>
__global__ __launch_bounds__(256) void tgemm(
    const __nv_bfloat16* __restrict__ ah, const __nv_bfloat16* __restrict__ al,
    const __nv_bfloat16* __restrict__ bh, const __nv_bfloat16* __restrict__ bl,
    const float* __restrict__ bias, float* __restrict__ of,
    __nv_bfloat16* __restrict__ oh, __nv_bfloat16* __restrict__ ol, float scale)
{
    extern __shared__ char sm[];
    const uint32_t sb = s2u(sm);
    const int tid = threadIdx.x, wid = tid >> 5, lane = tid & 31;
    const int bm = blockIdx.y * 128, bn = blockIdx.x * 128;

    if (wid == 0) { TC_ALLOC(sb, 128); TC_RELQ(); }
    if (tid == 0) { MBAR_INIT(sb + 8, 1); MBAR_INIT(sb + 16, 1); }
    __syncthreads();
    uint32_t tm;
    asm volatile("ld.shared.b32 %0, [%1];" : "=r"(tm) : "r"(sb));

    auto stage = [&](int kc, int buf) {
#pragma unroll
        for (int i = 0; i < 16; i++) {
            int idx = tid + i * 256;
            int t = idx >> 10, r = (idx >> 3) & 127, u = idx & 7;
            const __nv_bfloat16* src = (t == 0) ? ah : (t == 1) ? al : (t == 2) ? bh : bl;
            int grow = ((t < 2) ? bm : bn) + r;
            uint4 v = *(const uint4*)(src + (size_t)grow * 512 + kc * 64 + u * 8);
            *(uint4*)(sm + 1024 + buf * 65536 + t * 16384 + SWZ(r * 128 + u * 16)) = v;
        }
    };

    stage(0, 0); FPROXY(); __syncthreads();
    int cnt0 = 0, cnt1 = 0;
    for (int kc = 0; kc < 8; kc++) {
        int buf = kc & 1;
        if (wid == 0) {
            if (elect1()) {
                uint32_t ab = sb + 1024 + buf * 65536;
                uint64_t dah = dk(ab), dal = dk(ab + 16384);
                uint64_t dbh = dk(ab + 32768), dbl = dk(ab + 49152);
#pragma unroll
                for (int s = 0; s < 4; s++) mma16(tm, dah + 2*s, dbh + 2*s, ID_128, (kc > 0) || (s > 0));
#pragma unroll
                for (int s = 0; s < 4; s++) mma16(tm, dah + 2*s, dbl + 2*s, ID_128, 1);
#pragma unroll
                for (int s = 0; s < 4; s++) mma16(tm, dal + 2*s, dbh + 2*s, ID_128, 1);
                TC_COMMIT(sb + 8 + buf * 8);
            }
        }
        if (kc < 7) {
            if (kc >= 1) {
                int ob = buf ^ 1;
                int ph = (ob ? cnt1++ : cnt0++) & 1;
                MBAR_WAIT(sb + 8 + ob * 8, ph);
            }
            stage(kc + 1, buf ^ 1); FPROXY(); __syncthreads();
        }
    }
    MBAR_WAIT(sb + 16, cnt1 & 1);
    TC_FA();

    const int r = (wid & 3) * 32 + lane, cb = (wid >> 2) * 64;
    uint32_t u[64];
    LDTM32(u, tm + cb);
    LDTM32(u + 32, tm + cb + 32);
    TC_WLD(); TC_FB();
    float f[64];
#pragma unroll
    for (int j = 0; j < 64; j++)
        f[j] = scale * (__uint_as_float(u[j]) + bias[bn + cb + j]);
    if (MODE == 0) {
        float* p = of + (size_t)(bm + r) * 512 + bn + cb;
#pragma unroll
        for (int g = 0; g < 16; g++)
            *(float4*)(p + g * 4) = make_float4(f[g*4], f[g*4+1], f[g*4+2], f[g*4+3]);
    } else if (MODE == 1) {
        uint32_t hw[32], lw[32];
#pragma unroll
        for (int j = 0; j < 32; j++) {
            __nv_bfloat16 h0 = __float2bfloat16_rn(f[2*j]), h1 = __float2bfloat16_rn(f[2*j+1]);
            hw[j] = packh(h0, h1);
            lw[j] = packh(__float2bfloat16_rn(f[2*j]   - __bfloat162float(h0)),
                          __float2bfloat16_rn(f[2*j+1] - __bfloat162float(h1)));
        }
        size_t o = (size_t)(bm + r) * 512 + bn + cb;
#pragma unroll
        for (int g = 0; g < 8; g++) {
            *(uint4*)(oh + o + g * 8) = make_uint4(hw[g*4], hw[g*4+1], hw[g*4+2], hw[g*4+3]);
            *(uint4*)(ol + o + g * 8) = make_uint4(lw[g*4], lw[g*4+1], lw[g*4+2], lw[g*4+3]);
        }
    } else {
#pragma unroll
        for (int j = 0; j < 64; j++) {
            __nv_bfloat16 h0 = __float2bfloat16_rn(f[j]);
            __nv_bfloat16 l0 = __float2bfloat16_rn(f[j] - __bfloat162float(h0));
            size_t o = (size_t)(bn + cb + j) * 4096 + bm + r;
            oh[o] = h0;
            ol[o] = l0;
        }
    }
    __syncthreads();
    if (wid == 0) TC_DEALLOC(tm, 128);
}

// ------------------------- pipelined tcgen05 attention ---------------------
// smem: [0:32) ptr+mbars, [32:1568) lsum[3][128], Q @2048 (32K),
// KV bufs @34816 (2 x 64K), PH @165888 (32K), PL @198656 (32K). total 231424.
#define A_Q   2048
#define A_KV0 34816
#define A_PH  165888
#define A_PL  198656
#define A_SMEM 231424
#define NT 48

__global__ __launch_bounds__(256) void attn(
    const __nv_bfloat16* __restrict__ qh, const __nv_bfloat16* __restrict__ ql,
    const __nv_bfloat16* __restrict__ kh, const __nv_bfloat16* __restrict__ kl,
    const __nv_bfloat16* __restrict__ vth, const __nv_bfloat16* __restrict__ vtl,
    __nv_bfloat16* __restrict__ oh, __nv_bfloat16* __restrict__ ol)
{
    extern __shared__ char sm[];
    const uint32_t sb = s2u(sm);
    float* lsumf = (float*)(sm + 32);
    const int tid = threadIdx.x, wid = tid >> 5, lane = tid & 31;
    const int q0 = blockIdx.x * 128, h = blockIdx.y, b = blockIdx.z;

    if (wid == 0) { TC_ALLOC(sb, 512); TC_RELQ(); }
    if (tid == 0) { MBAR_INIT(sb + 8, 1); MBAR_INIT(sb + 16, 1); }
    if (tid < 128) { lsumf[tid] = 0.f; lsumf[128 + tid] = 0.f; lsumf[256 + tid] = 0.f; }
    __syncthreads();
    uint32_t tm;
    asm volatile("ld.shared.b32 %0, [%1];" : "=r"(tm) : "r"(sb));
    const uint32_t tmo = tm + 256;   // 3 x 64 O cols

    // stage tile g1 (src=g1/16, kt=g1%16) into buf (cp.async, one group)
    auto ldkv = [&](int g1, int buf) {
        int srcI = g1 >> 4, kt = g1 & 15;
        const size_t kvb = ((size_t)(srcI * 2 + b)) * 2048 * 512 + h * 64;
        const size_t vtb = ((size_t)(srcI * 512 + h * 64)) * 4096 + b * 2048;
        uint32_t base = sb + A_KV0 + buf * 65536;
#pragma unroll
        for (int i = 0; i < 16; i++) {
            int idx = tid + i * 256;
            int mat = idx >> 10, rem = idx & 1023;
            if (mat < 2) {
                int rr = rem >> 3, u = rem & 7;
                const __nv_bfloat16* s0 = mat ? kl : kh;
                CPA16(base + mat * 16384 + SWZ(rr * 128 + u * 16),
                      s0 + kvb + (size_t)(kt * 128 + rr) * 512 + u * 8);
            } else {
                int d = rem >> 4, u = rem & 15;
                const __nv_bfloat16* s0 = (mat == 2) ? vth : vtl;
                CPA16(base + 32768 + (mat - 2) * 16384 + (u >> 3) * 8192 + SWZ(d * 128 + (u & 7) * 16),
                      s0 + vtb + (size_t)d * 4096 + kt * 128 + u * 8);
            }
        }
        CPA_COMMIT();
    };

    // Q tile hi/lo (once)
#pragma unroll
    for (int i = 0; i < 8; i++) {
        int idx = tid + i * 256;
        int t = idx >> 10, r = (idx >> 3) & 127, u = idx & 7;
        const __nv_bfloat16* src = t ? ql : qh;
        uint4 v = *(const uint4*)(src + (size_t)(b * 2048 + q0 + r) * 512 + h * 64 + u * 8);
        *(uint4*)(sm + A_Q + t * 16384 + SWZ(r * 128 + u * 16)) = v;
    }

    // prologue: tile 0 staged, S(0) issued
    ldkv(0, 0);
    CPA_WAIT0(); FPROXY(); __syncthreads();
    if (wid == 0 && elect1()) {
        uint64_t dqh = dk(sb + A_Q), dql = dk(sb + A_Q + 16384);
        uint64_t dkh = dk(sb + A_KV0), dkl = dk(sb + A_KV0 + 16384);
#pragma unroll
        for (int s = 0; s < 4; s++) mma16(tm, dqh + 2*s, dkh + 2*s, ID_128, s > 0);
#pragma unroll
        for (int s = 0; s < 4; s++) mma16(tm, dqh + 2*s, dkl + 2*s, ID_128, 1);
#pragma unroll
        for (int s = 0; s < 4; s++) mma16(tm, dql + 2*s, dkh + 2*s, ID_128, 1);
        TC_COMMIT(sb + 8);
    }

    const int r = (wid & 3) * 32 + lane;
    const int cb = (wid >> 2) * 64;
    const int cb2 = (wid >> 2) * 32;
    int scnt = 0, pvcnt = 0;

    for (int g = 0; g < NT; g++) {
        const int srcI = g >> 4;
        MBAR_WAIT(sb + 8, scnt & 1); scnt++;       // S(g) done (implies PV(g-2) done)
        TC_FA();

        uint32_t u0[64];
        LDTM32(u0, tm + (g & 1) * 128 + cb);
        LDTM32(u0 + 32, tm + (g & 1) * 128 + cb + 32);
        TC_WLD(); TC_FB();

        // exp + split-pack in registers (overlaps PV(g-1) on tensor pipe)
        float ps = 0.0f;
#pragma unroll
        for (int j = 0; j < 32; j++) {
            float e0 = __expf(fminf(__uint_as_float(u0[2*j]),     60.f));
            float e1 = __expf(fminf(__uint_as_float(u0[2*j + 1]), 60.f));
            ps += e0 + e1;
            uint32_t hw = pack2(e0, e1);
            float h0 = __uint_as_float(hw << 16);
            float h1 = __uint_as_float(hw & 0xffff0000u);
            u0[2*j]     = hw;
            u0[2*j + 1] = pack2(e0 - h0, e1 - h1);
        }

        if (g >= 1) { MBAR_WAIT(sb + 16, pvcnt & 1); pvcnt++; }   // PV(g-1) done: P + old V free
        if (g + 1 < NT) ldkv(g + 1, (g + 1) & 1);

        // store P hi/lo (blocked 2 atom-cols)
#pragma unroll
        for (int j4 = 0; j4 < 16; j4++) {
            int t = cb + j4 * 4;
            uint32_t off = (uint32_t)((t >> 6) * 16384) + SWZ(r * 128 + (t & 63) * 2);
            *(uint2*)(sm + A_PH + off) = make_uint2(u0[j4*4],     u0[j4*4 + 2]);
            *(uint2*)(sm + A_PL + off) = make_uint2(u0[j4*4 + 1], u0[j4*4 + 3]);
        }
        atomicAdd(&lsumf[srcI * 128 + r], ps);
        CPA_WAIT0(); FPROXY(); __syncthreads();

        if (wid == 0 && elect1()) {
            if (g + 1 < NT) {                       // S(g+1)
                uint32_t kb = sb + A_KV0 + ((g + 1) & 1) * 65536;
                uint64_t dqh = dk(sb + A_Q), dql = dk(sb + A_Q + 16384);
                uint64_t dkh = dk(kb), dkl = dk(kb + 16384);
                uint32_t tms = tm + ((g + 1) & 1) * 128;
#pragma unroll
                for (int s = 0; s < 4; s++) mma16(tms, dqh + 2*s, dkh + 2*s, ID_128, s > 0);
#pragma unroll
                for (int s = 0; s < 4; s++) mma16(tms, dqh + 2*s, dkl + 2*s, ID_128, 1);
#pragma unroll
                for (int s = 0; s < 4; s++) mma16(tms, dql + 2*s, dkh + 2*s, ID_128, 1);
                TC_COMMIT(sb + 8);
            }
            {                                       // PV(g)
                uint32_t vb0 = sb + A_KV0 + (g & 1) * 65536 + 32768;
                uint64_t dph = dk(sb + A_PH), dpl = dk(sb + A_PL);
                uint64_t dvh = dk(vb0), dvl = dk(vb0 + 16384);
                uint32_t dsto = tmo + srcI * 64;
                int accbase = (g & 15) > 0;
#pragma unroll
                for (int s = 0; s < 8; s++) {
                    uint64_t pa = (uint64_t)((s >> 2) * 1024 + (s & 3) * 2);
                    uint64_t vb = (uint64_t)((s >> 2) * 512  + (s & 3) * 2);
                    mma16(dsto, dph + pa, dvh + vb, ID_PV, accbase || (s > 0));
                }
#pragma unroll
                for (int s = 0; s < 8; s++) {
                    uint64_t pa = (uint64_t)((s >> 2) * 1024 + (s & 3) * 2);
                    uint64_t vb = (uint64_t)((s >> 2) * 512  + (s & 3) * 2);
                    mma16(dsto, dph + pa, dvl + vb, ID_PV, 1);
                }
#pragma unroll
                for (int s = 0; s < 8; s++) {
                    uint64_t pa = (uint64_t)((s >> 2) * 1024 + (s & 3) * 2);
                    uint64_t vb = (uint64_t)((s >> 2) * 512  + (s & 3) * 2);
                    mma16(dsto, dpl + pa, dvh + vb, ID_PV, 1);
                }
                TC_COMMIT(sb + 16);
            }
        }
    }

    MBAR_WAIT(sb + 16, pvcnt & 1); pvcnt++;   // PV(47)
    TC_FA();
    __syncthreads();                          // lsum atomics complete

    float oacc[32];
#pragma unroll
    for (int j = 0; j < 32; j++) oacc[j] = 0.0f;
#pragma unroll
    for (int srcI = 0; srcI < 3; srcI++) {
        uint32_t uo[32];
        LDTM32(uo, tmo + srcI * 64 + cb2);
        TC_WLD();
        float inv = 1.0f / lsumf[srcI * 128 + r];
#pragma unroll
        for (int j = 0; j < 32; j++) oacc[j] += __uint_as_float(uo[j]) * inv;
    }
    TC_FB();

    uint32_t hw[16], lw[16];
#pragma unroll
    for (int j = 0; j < 16; j++) {
        __nv_bfloat16 h0 = __float2bfloat16_rn(oacc[2*j]), h1 = __float2bfloat16_rn(oacc[2*j+1]);
        hw[j] = packh(h0, h1);
        lw[j] = packh(__float2bfloat16_rn(oacc[2*j]   - __bfloat162float(h0)),
                      __float2bfloat16_rn(oacc[2*j+1] - __bfloat162float(h1)));
    }
    size_t o = (size_t)(b * 2048 + q0 + r) * 512 + h * 64 + cb2;
#pragma unroll
    for (int g2 = 0; g2 < 4; g2++) {
        *(uint4*)(oh + o + g2 * 8) = make_uint4(hw[g2*4], hw[g2*4+1], hw[g2*4+2], hw[g2*4+3]);
        *(uint4*)(ol + o + g2 * 8) = make_uint4(lw[g2*4], lw[g2*4+1], lw[g2*4+2], lw[g2*4+3]);
    }
    __syncthreads();
    if (wid == 0) TC_DEALLOC(tm, 512);
}

// ---------------------------------------------------------------------------
extern "C" void kernel_launch(void* const* d_in, const int* in_sizes, int n_in,
                              void* d_out, int out_size)
{
    const float* x  = (const float*)d_in[0];
    const float* y  = (const float*)d_in[1];
    const float* Wq = (const float*)d_in[2];
    const float* bq = (const float*)d_in[3];
    const float* Wk = (const float*)d_in[4];
    const float* bk = (const float*)d_in[5];
    const float* Wv = (const float*)d_in[6];
    const float* bv = (const float*)d_in[7];
    const float* Wp = (const float*)d_in[8];
    const float* bp = (const float*)d_in[9];
    float* out = (float*)d_out;

    __nv_bfloat16 *xh, *xl, *yh, *yl, *wh, *wl, *Qh, *Ql, *Kh, *Kl, *Vth, *Vtl, *Oh, *Ol;
    cudaGetSymbolAddress((void**)&xh, g_xh);  cudaGetSymbolAddress((void**)&xl, g_xl);
    cudaGetSymbolAddress((void**)&yh, g_yh);  cudaGetSymbolAddress((void**)&yl, g_yl);
    cudaGetSymbolAddress((void**)&wh, g_wh);  cudaGetSymbolAddress((void**)&wl, g_wl);
    cudaGetSymbolAddress((void**)&Qh, g_qh);  cudaGetSymbolAddress((void**)&Ql, g_ql);
    cudaGetSymbolAddress((void**)&Kh, g_kh);  cudaGetSymbolAddress((void**)&Kl, g_kl);
    cudaGetSymbolAddress((void**)&Vth, g_vth); cudaGetSymbolAddress((void**)&Vtl, g_vtl);
    cudaGetSymbolAddress((void**)&Oh, g_oh);  cudaGetSymbolAddress((void**)&Ol, g_ol);

    const int GSM = 1024 + 2 * 4 * 16384;
    cudaFuncSetAttribute(tgemm<0>, cudaFuncAttributeMaxDynamicSharedMemorySize, GSM);
    cudaFuncSetAttribute(tgemm<1>, cudaFuncAttributeMaxDynamicSharedMemorySize, GSM);
    cudaFuncSetAttribute(tgemm<2>, cudaFuncAttributeMaxDynamicSharedMemorySize, GSM);
    cudaFuncSetAttribute(attn,     cudaFuncAttributeMaxDynamicSharedMemorySize, A_SMEM);

    splitk<<<512, 256>>>(x, xh, xl, ELEM_X / 4);
    splitk<<<1024, 256>>>(y, yh, yl, ELEM_Y / 4);
    wtsk<<<dim3(16, 16, 1), dim3(32, 32)>>>(Wq, wh,            wl);
    wtsk<<<dim3(16, 16, 3), dim3(32, 32)>>>(Wk, wh + 1 * WSTR, wl + 1 * WSTR);
    wtsk<<<dim3(16, 16, 3), dim3(32, 32)>>>(Wv, wh + 4 * WSTR, wl + 4 * WSTR);
    wtsk<<<dim3(16, 16, 1), dim3(32, 32)>>>(Wp, wh + 7 * WSTR, wl + 7 * WSTR);

    dim3 gg(4, 32), gb(256);
    tgemm<1><<<gg, gb, GSM>>>(xh, xl, wh, wl, bq, nullptr, Qh, Ql, 0.125f);
    for (int i = 0; i < NSRC; i++) {
        size_t off = (size_t)i * 2 * 2048 * 512;
        tgemm<1><<<gg, gb, GSM>>>(yh + off, yl + off, wh + (1 + i) * WSTR, wl + (1 + i) * WSTR,
                                  bk + i * 512, nullptr, Kh + off, Kl + off, 1.0f);
        tgemm<2><<<gg, gb, GSM>>>(yh + off, yl + off, wh + (4 + i) * WSTR, wl + (4 + i) * WSTR,
                                  bv + i * 512, nullptr, Vth + off, Vtl + off, 1.0f);
    }
    attn<<<dim3(16, 8, 2), gb, A_SMEM>>>(Qh, Ql, Kh, Kl, Vth, Vtl, Oh, Ol);
    tgemm<0><<<gg, gb, GSM>>>(Oh, Ol, wh + 7 * WSTR, wl + 7 * WSTR, bp, out, nullptr, nullptr, 1.0f);
}

// round 9
// speedup vs baseline: 6.2046x; 1.1072x over previous
#include <cuda_runtime.h>
#include <cuda_bf16.h>
#include <stdint.h>

#define NSRC 3
#define ELEM_X (2*2048*512)
#define ELEM_Y (3*2*2048*512)
#define WSTR   (512*512)

__device__ __nv_bfloat16 g_xh[ELEM_X], g_xl[ELEM_X];
__device__ __nv_bfloat16 g_yh[ELEM_Y], g_yl[ELEM_Y];
__device__ __nv_bfloat16 g_wh[8*WSTR], g_wl[8*WSTR];
__device__ __nv_bfloat16 g_qh[ELEM_X], g_ql[ELEM_X];
__device__ __nv_bfloat16 g_kh[ELEM_Y], g_kl[ELEM_Y];
__device__ __nv_bfloat16 g_vth[ELEM_Y], g_vtl[ELEM_Y];   // V^T: [src*512+n][4096]
__device__ __nv_bfloat16 g_oh[ELEM_X], g_ol[ELEM_X];

#define SWZ(o) ((uint32_t)(o) ^ ((((uint32_t)(o)) >> 3) & 0x70u))
#define ID_128 0x8200490u   /* kind::f16 f32acc bf16 M=128 N=128 */
#define ID_PV  0x8100490u   /* kind::f16 f32acc bf16 M=128 N=64  */

#if defined(__CUDA_ARCH_FEAT_SM103_ALL) || defined(__CUDA_ARCH_FEAT_SM100_ALL) || !defined(__CUDA_ARCH__)
#define HAS_TC5 1
#else
#define HAS_TC5 0
#endif

__device__ __forceinline__ uint32_t elect1() {
    uint32_t p;
    asm volatile("{\n\t.reg .pred p;\n\telect.sync _|p, 0xFFFFFFFF;\n\tselp.b32 %0,1,0,p;\n\t}" : "=r"(p));
    return p;
}
__device__ __forceinline__ uint32_t s2u(const void* p) {
    uint32_t a;
    asm("{ .reg .u64 t; cvta.to.shared.u64 t, %1; cvt.u32.u64 %0, t; }" : "=r"(a) : "l"(p));
    return a;
}
__device__ __forceinline__ uint64_t dk(uint32_t a) {
    return (2ull<<61)|(1ull<<46)|(64ull<<32)|(1ull<<16)|((uint64_t)(a>>4)&0x3FFFull);
}

#define MBAR_INIT(a,n) asm volatile("mbarrier.init.shared.b64 [%0], %1;" :: "r"(a), "r"(n) : "memory")
#define MBAR_WAIT(a,ph) asm volatile("{\n\t.reg .pred P1;\n\tLW%=:\n\t" \
    "mbarrier.try_wait.parity.acquire.cta.shared::cta.b64 P1, [%0], %1, 0x989680;\n\t" \
    "@P1 bra.uni LD%=;\n\tbra.uni LW%=;\n\tLD%=:\n\t}" :: "r"(a), "r"(ph) : "memory")
#define FPROXY()       asm volatile("fence.proxy.async.shared::cta;" ::: "memory")
#define CPA16(d,s)     asm volatile("cp.async.cg.shared.global [%0], [%1], 16;" :: "r"(d), "l"(s))
#define CPA_COMMIT()   asm volatile("cp.async.commit_group;" ::: "memory")
#define CPA_WAIT0()    asm volatile("cp.async.wait_group 0;" ::: "memory")
#define CPA_WAIT1()    asm volatile("cp.async.wait_group 1;" ::: "memory")
#define CPA_WAIT2()    asm volatile("cp.async.wait_group 2;" ::: "memory")

#if HAS_TC5
__device__ __forceinline__ void mma16(uint32_t d, uint64_t a, uint64_t b, uint32_t id, uint32_t acc) {
    asm volatile("{\n\t.reg .pred p;\n\tsetp.ne.u32 p, %4, 0;\n\t"
        "tcgen05.mma.cta_group::1.kind::f16 [%0], %1, %2, %3, {%5,%5,%5,%5}, p;\n\t}"
        :: "r"(d), "l"(a), "l"(b), "r"(id), "r"(acc), "r"(0u) : "memory");
}
#define TC_ALLOC(a,n)  asm volatile("tcgen05.alloc.cta_group::1.sync.aligned.shared::cta.b32 [%0], %1;" :: "r"(a), "r"(n) : "memory")
#define TC_RELQ()      asm volatile("tcgen05.relinquish_alloc_permit.cta_group::1.sync.aligned;")
#define TC_DEALLOC(t,n) asm volatile("tcgen05.dealloc.cta_group::1.sync.aligned.b32 %0, %1;" :: "r"(t), "r"(n))
#define TC_COMMIT(a)   asm volatile("tcgen05.commit.cta_group::1.mbarrier::arrive::one.shared::cluster.b64 [%0];" :: "r"(a) : "memory")
#define TC_FA()        asm volatile("tcgen05.fence::after_thread_sync;" ::: "memory")
#define TC_FB()        asm volatile("tcgen05.fence::before_thread_sync;" ::: "memory")
#define TC_WLD()       asm volatile("tcgen05.wait::ld.sync.aligned;" ::: "memory")
#define LDTM32(r, a) asm volatile( \
    "tcgen05.ld.sync.aligned.32x32b.x32.b32 " \
    "{%0,%1,%2,%3,%4,%5,%6,%7,%8,%9,%10,%11,%12,%13,%14,%15," \
    "%16,%17,%18,%19,%20,%21,%22,%23,%24,%25,%26,%27,%28,%29,%30,%31}, [%32];" \
    : "=r"((r)[0]),"=r"((r)[1]),"=r"((r)[2]),"=r"((r)[3]),"=r"((r)[4]),"=r"((r)[5]),"=r"((r)[6]),"=r"((r)[7]), \
      "=r"((r)[8]),"=r"((r)[9]),"=r"((r)[10]),"=r"((r)[11]),"=r"((r)[12]),"=r"((r)[13]),"=r"((r)[14]),"=r"((r)[15]), \
      "=r"((r)[16]),"=r"((r)[17]),"=r"((r)[18]),"=r"((r)[19]),"=r"((r)[20]),"=r"((r)[21]),"=r"((r)[22]),"=r"((r)[23]), \
      "=r"((r)[24]),"=r"((r)[25]),"=r"((r)[26]),"=r"((r)[27]),"=r"((r)[28]),"=r"((r)[29]),"=r"((r)[30]),"=r"((r)[31]) \
    : "r"(a))
#else
__device__ __forceinline__ void mma16(uint32_t, uint64_t, uint64_t, uint32_t, uint32_t) { __trap(); }
#define TC_ALLOC(a,n)   __trap()
#define TC_RELQ()       __trap()
#define TC_DEALLOC(t,n) __trap()
#define TC_COMMIT(a)    __trap()
#define TC_FA()         ((void)0)
#define TC_FB()         ((void)0)
#define TC_WLD()        ((void)0)
#define LDTM32(r, a) do { _Pragma("unroll") for (int _i = 0; _i < 32; _i++) (r)[_i] = 0u; __trap(); } while (0)
#endif

__device__ __forceinline__ uint32_t packh(__nv_bfloat16 a, __nv_bfloat16 b) {
    __nv_bfloat162 v; v.x = a; v.y = b;
    return *reinterpret_cast<uint32_t*>(&v);
}
__device__ __forceinline__ uint32_t pack2(float lo, float hi) {
    uint32_t r;
    asm("cvt.rn.bf16x2.f32 %0, %1, %2;" : "=r"(r) : "f"(hi), "f"(lo));
    return r;
}

// ------------------------- prep kernels -----------------------------------
__global__ void splitk(const float* __restrict__ in, __nv_bfloat16* __restrict__ oh,
                       __nv_bfloat16* __restrict__ ol, int n4) {
    for (int i = blockIdx.x * blockDim.x + threadIdx.x; i < n4; i += gridDim.x * blockDim.x) {
        float4 v = ((const float4*)in)[i];
        __nv_bfloat16 h0 = __float2bfloat16_rn(v.x), h1 = __float2bfloat16_rn(v.y);
        __nv_bfloat16 h2 = __float2bfloat16_rn(v.z), h3 = __float2bfloat16_rn(v.w);
        __nv_bfloat16 l0 = __float2bfloat16_rn(v.x - __bfloat162float(h0));
        __nv_bfloat16 l1 = __float2bfloat16_rn(v.y - __bfloat162float(h1));
        __nv_bfloat16 l2 = __float2bfloat16_rn(v.z - __bfloat162float(h2));
        __nv_bfloat16 l3 = __float2bfloat16_rn(v.w - __bfloat162float(h3));
        *(uint2*)(oh + 4 * (size_t)i) = make_uint2(packh(h0, h1), packh(h2, h3));
        *(uint2*)(ol + 4 * (size_t)i) = make_uint2(packh(l0, l1), packh(l2, l3));
    }
}

__global__ void wtsk(const float* __restrict__ W, __nv_bfloat16* __restrict__ th,
                     __nv_bfloat16* __restrict__ tl) {
    __shared__ float t[32][33];
    int m = blockIdx.z;
    int k0 = blockIdx.x * 32, n0 = blockIdx.y * 32;
    const float* Wm = W + (size_t)m * WSTR;
    t[threadIdx.y][threadIdx.x] = Wm[(size_t)(k0 + threadIdx.y) * 512 + n0 + threadIdx.x];
    __syncthreads();
    float v = t[threadIdx.x][threadIdx.y];
    size_t di = (size_t)m * WSTR + (size_t)(n0 + threadIdx.y) * 512 + k0 + threadIdx.x;
    __nv_bfloat16 h = __float2bfloat16_rn(v);
    th[di] = h;
    tl[di] = __float2bfloat16_rn(v - __bfloat162float(h));
}

// ------------------------- tcgen05 GEMM (triple-buffered cp.async) ---------
template <int MODE>
__global__ __launch_bounds__(256) void tgemm(
    const __nv_bfloat16* __restrict__ ah, const __nv_bfloat16* __restrict__ al,
    const __nv_bfloat16* __restrict__ bh, const __nv_bfloat16* __restrict__ bl,
    const float* __restrict__ bias, float* __restrict__ of,
    __nv_bfloat16* __restrict__ oh, __nv_bfloat16* __restrict__ ol, float scale)
{
    extern __shared__ char sm[];
    const uint32_t sb = s2u(sm);
    const int tid = threadIdx.x, wid = tid >> 5, lane = tid & 31;
    const int bm = blockIdx.y * 128, bn = blockIdx.x * 128;

    if (wid == 0) { TC_ALLOC(sb, 128); TC_RELQ(); }
    if (tid == 0) MBAR_INIT(sb + 8, 1);
    __syncthreads();
    uint32_t tm;
    asm volatile("ld.shared.b32 %0, [%1];" : "=r"(tm) : "r"(sb));

    auto stage = [&](int kc, int buf) {
#pragma unroll
        for (int i = 0; i < 16; i++) {
            int idx = tid + i * 256;
            int t = idx >> 10, r = (idx >> 3) & 127, u = idx & 7;
            const __nv_bfloat16* src = (t == 0) ? ah : (t == 1) ? al : (t == 2) ? bh : bl;
            int grow = ((t < 2) ? bm : bn) + r;
            CPA16(sb + 1024 + buf * 65536 + t * 16384 + SWZ(r * 128 + u * 16),
                  src + (size_t)grow * 512 + kc * 64 + u * 8);
        }
        CPA_COMMIT();
    };

    stage(0, 0);
    stage(1, 1);
    for (int kc = 0; kc < 8; kc++) {
        int buf = kc % 3;
        if (kc >= 1) MBAR_WAIT(sb + 8, (kc - 1) & 1);
        if (kc + 2 < 8) stage(kc + 2, (kc + 2) % 3);
        if (kc < 6) CPA_WAIT2(); else if (kc == 6) CPA_WAIT1(); else CPA_WAIT0();
        FPROXY(); __syncthreads();
        if (wid == 0 && elect1()) {
            uint32_t ab = sb + 1024 + buf * 65536;
            uint64_t dah = dk(ab), dal = dk(ab + 16384);
            uint64_t dbh = dk(ab + 32768), dbl = dk(ab + 49152);
#pragma unroll
            for (int s = 0; s < 4; s++) mma16(tm, dah + 2*s, dbh + 2*s, ID_128, (kc > 0) || (s > 0));
#pragma unroll
            for (int s = 0; s < 4; s++) mma16(tm, dah + 2*s, dbl + 2*s, ID_128, 1);
#pragma unroll
            for (int s = 0; s < 4; s++) mma16(tm, dal + 2*s, dbh + 2*s, ID_128, 1);
            TC_COMMIT(sb + 8);
        }
    }
    MBAR_WAIT(sb + 8, 1);
    TC_FA();

    const int r = (wid & 3) * 32 + lane, cb = (wid >> 2) * 64;
    uint32_t u[64];
    LDTM32(u, tm + cb);
    LDTM32(u + 32, tm + cb + 32);
    TC_WLD(); TC_FB();
    float f[64];
#pragma unroll
    for (int j = 0; j < 64; j++)
        f[j] = scale * (__uint_as_float(u[j]) + bias[bn + cb + j]);
    if (MODE == 0) {
        float* p = of + (size_t)(bm + r) * 512 + bn + cb;
#pragma unroll
        for (int g = 0; g < 16; g++)
            *(float4*)(p + g * 4) = make_float4(f[g*4], f[g*4+1], f[g*4+2], f[g*4+3]);
    } else if (MODE == 1) {
        uint32_t hw[32], lw[32];
#pragma unroll
        for (int j = 0; j < 32; j++) {
            __nv_bfloat16 h0 = __float2bfloat16_rn(f[2*j]), h1 = __float2bfloat16_rn(f[2*j+1]);
            hw[j] = packh(h0, h1);
            lw[j] = packh(__float2bfloat16_rn(f[2*j]   - __bfloat162float(h0)),
                          __float2bfloat16_rn(f[2*j+1] - __bfloat162float(h1)));
        }
        size_t o = (size_t)(bm + r) * 512 + bn + cb;
#pragma unroll
        for (int g = 0; g < 8; g++) {
            *(uint4*)(oh + o + g * 8) = make_uint4(hw[g*4], hw[g*4+1], hw[g*4+2], hw[g*4+3]);
            *(uint4*)(ol + o + g * 8) = make_uint4(lw[g*4], lw[g*4+1], lw[g*4+2], lw[g*4+3]);
        }
    } else {
#pragma unroll
        for (int j = 0; j < 64; j++) {
            __nv_bfloat16 h0 = __float2bfloat16_rn(f[j]);
            __nv_bfloat16 l0 = __float2bfloat16_rn(f[j] - __bfloat162float(h0));
            size_t o = (size_t)(bn + cb + j) * 4096 + bm + r;
            oh[o] = h0;
            ol[o] = l0;
        }
    }
    __syncthreads();
    if (wid == 0) TC_DEALLOC(tm, 128);
}
#define GSM (1024 + 3 * 65536)

// ------------------------- pipelined tcgen05 attention ---------------------
// smem: hdr 2048 (ptr/mbars/lsum[3][128]), Q @2048 (32K), K bufs @34816 (2x32K),
// V bufs @100352 (2x32K), PH @165888 (32K), PL @198656 (32K) = 231424.
#define A_Q   2048
#define A_K0  34816
#define A_V0  100352
#define A_PH  165888
#define A_PL  198656
#define A_SMEM 231424
#define NT 48

__global__ __launch_bounds__(256) void attn(
    const __nv_bfloat16* __restrict__ qh, const __nv_bfloat16* __restrict__ ql,
    const __nv_bfloat16* __restrict__ kh, const __nv_bfloat16* __restrict__ kl,
    const __nv_bfloat16* __restrict__ vth, const __nv_bfloat16* __restrict__ vtl,
    __nv_bfloat16* __restrict__ oh, __nv_bfloat16* __restrict__ ol)
{
    extern __shared__ char sm[];
    const uint32_t sb = s2u(sm);
    float* lsumf = (float*)(sm + 32);
    const int tid = threadIdx.x, wid = tid >> 5, lane = tid & 31;
    const int q0 = blockIdx.x * 128, h = blockIdx.y, b = blockIdx.z;

    if (wid == 0) { TC_ALLOC(sb, 512); TC_RELQ(); }
    if (tid == 0) { MBAR_INIT(sb + 8, 1); MBAR_INIT(sb + 16, 1); }
    if (tid < 128) { lsumf[tid] = 0.f; lsumf[128 + tid] = 0.f; lsumf[256 + tid] = 0.f; }
    __syncthreads();
    uint32_t tm;
    asm volatile("ld.shared.b32 %0, [%1];" : "=r"(tm) : "r"(sb));
    const uint32_t tmo = tm + 256;

    auto ldK = [&](int g1, int buf) {      // 8 x CPA16 per thread, one group
        int srcI = g1 >> 4, kt = g1 & 15;
        const size_t kvb = ((size_t)(srcI * 2 + b)) * 2048 * 512 + h * 64;
        uint32_t base = sb + A_K0 + buf * 32768;
#pragma unroll
        for (int i = 0; i < 8; i++) {
            int idx = tid + i * 256;
            int mat = idx >> 10, rem = idx & 1023;
            int rr = rem >> 3, u = rem & 7;
            const __nv_bfloat16* s0 = mat ? kl : kh;
            CPA16(base + mat * 16384 + SWZ(rr * 128 + u * 16),
                  s0 + kvb + (size_t)(kt * 128 + rr) * 512 + u * 8);
        }
        CPA_COMMIT();
    };
    auto ldV = [&](int g1, int buf) {
        int srcI = g1 >> 4, kt = g1 & 15;
        const size_t vtb = ((size_t)(srcI * 512 + h * 64)) * 4096 + b * 2048;
        uint32_t base = sb + A_V0 + buf * 32768;
#pragma unroll
        for (int i = 0; i < 8; i++) {
            int idx = tid + i * 256;
            int mat = idx >> 10, rem = idx & 1023;
            int d = rem >> 4, u = rem & 15;
            const __nv_bfloat16* s0 = mat ? vtl : vth;
            CPA16(base + mat * 16384 + (u >> 3) * 8192 + SWZ(d * 128 + (u & 7) * 16),
                  s0 + vtb + (size_t)d * 4096 + kt * 128 + u * 8);
        }
        CPA_COMMIT();
    };

    // Q tile hi/lo (once, regular stores)
#pragma unroll
    for (int i = 0; i < 8; i++) {
        int idx = tid + i * 256;
        int t = idx >> 10, r = (idx >> 3) & 127, u = idx & 7;
        const __nv_bfloat16* src = t ? ql : qh;
        uint4 v = *(const uint4*)(src + (size_t)(b * 2048 + q0 + r) * 512 + h * 64 + u * 8);
        *(uint4*)(sm + A_Q + t * 16384 + SWZ(r * 128 + u * 16)) = v;
    }

    // prologue: K(0),V(0),K(1) staged; S(0) issued
    ldK(0, 0); ldV(0, 0); ldK(1, 1);
    CPA_WAIT0(); FPROXY(); __syncthreads();
    if (wid == 0 && elect1()) {
        uint64_t dqh = dk(sb + A_Q), dql = dk(sb + A_Q + 16384);
        uint64_t dkh = dk(sb + A_K0), dkl = dk(sb + A_K0 + 16384);
#pragma unroll
        for (int s = 0; s < 4; s++) mma16(tm, dqh + 2*s, dkh + 2*s, ID_128, s > 0);
#pragma unroll
        for (int s = 0; s < 4; s++) mma16(tm, dqh + 2*s, dkl + 2*s, ID_128, 1);
#pragma unroll
        for (int s = 0; s < 4; s++) mma16(tm, dql + 2*s, dkh + 2*s, ID_128, 1);
        TC_COMMIT(sb + 8);
    }

    const int r = (wid & 3) * 32 + lane;
    const int cb = (wid >> 2) * 64;
    const int cb2 = (wid >> 2) * 32;
    int scnt = 0, pvcnt = 0;

    for (int g = 0; g < NT; g++) {
        const int srcI = g >> 4;
        MBAR_WAIT(sb + 8, scnt & 1); scnt++;        // S(g) done
        TC_FA();
        CPA_WAIT0(); FPROXY(); __syncthreads();     // K(g+1)/V(g) resident

        if (g + 1 < NT && wid == 0 && elect1()) {   // S(g+1) EARLY (key change)
            uint32_t kb = sb + A_K0 + ((g + 1) & 1) * 32768;
            uint64_t dqh = dk(sb + A_Q), dql = dk(sb + A_Q + 16384);
            uint64_t dkh = dk(kb), dkl = dk(kb + 16384);
            uint32_t tms = tm + ((g + 1) & 1) * 128;
#pragma unroll
            for (int s = 0; s < 4; s++) mma16(tms, dqh + 2*s, dkh + 2*s, ID_128, s > 0);
#pragma unroll
            for (int s = 0; s < 4; s++) mma16(tms, dqh + 2*s, dkl + 2*s, ID_128, 1);
#pragma unroll
            for (int s = 0; s < 4; s++) mma16(tms, dql + 2*s, dkh + 2*s, ID_128, 1);
            TC_COMMIT(sb + 8);
        }

        uint32_t u0[64];
        LDTM32(u0, tm + (g & 1) * 128 + cb);
        LDTM32(u0 + 32, tm + (g & 1) * 128 + cb + 32);
        TC_WLD(); TC_FB();

        if (g + 2 < NT) ldK(g + 2, g & 1);          // K buffer freed by S(g)

        float ps = 0.0f;                             // exp overlaps S(g+1)/PV(g-1)
#pragma unroll
        for (int j = 0; j < 32; j++) {
            float e0 = __expf(fminf(__uint_as_float(u0[2*j]),     60.f));
            float e1 = __expf(fminf(__uint_as_float(u0[2*j + 1]), 60.f));
            ps += e0 + e1;
            uint32_t hw = pack2(e0, e1);
            float h0 = __uint_as_float(hw << 16);
            float h1 = __uint_as_float(hw & 0xffff0000u);
            u0[2*j]     = hw;
            u0[2*j + 1] = pack2(e0 - h0, e1 - h1);
        }

        if (g >= 1) { MBAR_WAIT(sb + 16, pvcnt & 1); pvcnt++; }   // PV(g-1) done
        if (g + 1 < NT) ldV(g + 1, (g + 1) & 1);    // V buffer freed by PV(g-1)

#pragma unroll
        for (int j4 = 0; j4 < 16; j4++) {
            int t = cb + j4 * 4;
            uint32_t off = (uint32_t)((t >> 6) * 16384) + SWZ(r * 128 + (t & 63) * 2);
            *(uint2*)(sm + A_PH + off) = make_uint2(u0[j4*4],     u0[j4*4 + 2]);
            *(uint2*)(sm + A_PL + off) = make_uint2(u0[j4*4 + 1], u0[j4*4 + 3]);
        }
        atomicAdd(&lsumf[srcI * 128 + r], ps);
        FPROXY(); __syncthreads();

        if (wid == 0 && elect1()) {                 // PV(g)
            uint32_t vb0 = sb + A_V0 + (g & 1) * 32768;
            uint64_t dph = dk(sb + A_PH), dpl = dk(sb + A_PL);
            uint64_t dvh = dk(vb0), dvl = dk(vb0 + 16384);
            uint32_t dsto = tmo + srcI * 64;
            int accbase = (g & 15) > 0;
#pragma unroll
            for (int s = 0; s < 8; s++) {
                uint64_t pa = (uint64_t)((s >> 2) * 1024 + (s & 3) * 2);
                uint64_t vb = (uint64_t)((s >> 2) * 512  + (s & 3) * 2);
                mma16(dsto, dph + pa, dvh + vb, ID_PV, accbase || (s > 0));
            }
#pragma unroll
            for (int s = 0; s < 8; s++) {
                uint64_t pa = (uint64_t)((s >> 2) * 1024 + (s & 3) * 2);
                uint64_t vb = (uint64_t)((s >> 2) * 512  + (s & 3) * 2);
                mma16(dsto, dph + pa, dvl + vb, ID_PV, 1);
            }
#pragma unroll
            for (int s = 0; s < 8; s++) {
                uint64_t pa = (uint64_t)((s >> 2) * 1024 + (s & 3) * 2);
                uint64_t vb = (uint64_t)((s >> 2) * 512  + (s & 3) * 2);
                mma16(dsto, dpl + pa, dvh + vb, ID_PV, 1);
            }
            TC_COMMIT(sb + 16);
        }
    }

    MBAR_WAIT(sb + 16, pvcnt & 1); pvcnt++;   // PV(47)
    TC_FA();
    __syncthreads();

    float oacc[32];
#pragma unroll
    for (int j = 0; j < 32; j++) oacc[j] = 0.0f;
#pragma unroll
    for (int srcI = 0; srcI < 3; srcI++) {
        uint32_t uo[32];
        LDTM32(uo, tmo + srcI * 64 + cb2);
        TC_WLD();
        float inv = 1.0f / lsumf[srcI * 128 + r];
#pragma unroll
        for (int j = 0; j < 32; j++) oacc[j] += __uint_as_float(uo[j]) * inv;
    }
    TC_FB();

    uint32_t hw[16], lw[16];
#pragma unroll
    for (int j = 0; j < 16; j++) {
        __nv_bfloat16 h0 = __float2bfloat16_rn(oacc[2*j]), h1 = __float2bfloat16_rn(oacc[2*j+1]);
        hw[j] = packh(h0, h1);
        lw[j] = packh(__float2bfloat16_rn(oacc[2*j]   - __bfloat162float(h0)),
                      __float2bfloat16_rn(oacc[2*j+1] - __bfloat162float(h1)));
    }
    size_t o = (size_t)(b * 2048 + q0 + r) * 512 + h * 64 + cb2;
#pragma unroll
    for (int g2 = 0; g2 < 4; g2++) {
        *(uint4*)(oh + o + g2 * 8) = make_uint4(hw[g2*4], hw[g2*4+1], hw[g2*4+2], hw[g2*4+3]);
        *(uint4*)(ol + o + g2 * 8) = make_uint4(lw[g2*4], lw[g2*4+1], lw[g2*4+2], lw[g2*4+3]);
    }
    __syncthreads();
    if (wid == 0) TC_DEALLOC(tm, 512);
}

// ---------------------------------------------------------------------------
extern "C" void kernel_launch(void* const* d_in, const int* in_sizes, int n_in,
                              void* d_out, int out_size)
{
    const float* x  = (const float*)d_in[0];
    const float* y  = (const float*)d_in[1];
    const float* Wq = (const float*)d_in[2];
    const float* bq = (const float*)d_in[3];
    const float* Wk = (const float*)d_in[4];
    const float* bk = (const float*)d_in[5];
    const float* Wv = (const float*)d_in[6];
    const float* bv = (const float*)d_in[7];
    const float* Wp = (const float*)d_in[8];
    const float* bp = (const float*)d_in[9];
    float* out = (float*)d_out;

    __nv_bfloat16 *xh, *xl, *yh, *yl, *wh, *wl, *Qh, *Ql, *Kh, *Kl, *Vth, *Vtl, *Oh, *Ol;
    cudaGetSymbolAddress((void**)&xh, g_xh);  cudaGetSymbolAddress((void**)&xl, g_xl);
    cudaGetSymbolAddress((void**)&yh, g_yh);  cudaGetSymbolAddress((void**)&yl, g_yl);
    cudaGetSymbolAddress((void**)&wh, g_wh);  cudaGetSymbolAddress((void**)&wl, g_wl);
    cudaGetSymbolAddress((void**)&Qh, g_qh);  cudaGetSymbolAddress((void**)&Ql, g_ql);
    cudaGetSymbolAddress((void**)&Kh, g_kh);  cudaGetSymbolAddress((void**)&Kl, g_kl);
    cudaGetSymbolAddress((void**)&Vth, g_vth); cudaGetSymbolAddress((void**)&Vtl, g_vtl);
    cudaGetSymbolAddress((void**)&Oh, g_oh);  cudaGetSymbolAddress((void**)&Ol, g_ol);

    cudaFuncSetAttribute(tgemm<0>, cudaFuncAttributeMaxDynamicSharedMemorySize, GSM);
    cudaFuncSetAttribute(tgemm<1>, cudaFuncAttributeMaxDynamicSharedMemorySize, GSM);
    cudaFuncSetAttribute(tgemm<2>, cudaFuncAttributeMaxDynamicSharedMemorySize, GSM);
    cudaFuncSetAttribute(attn,     cudaFuncAttributeMaxDynamicSharedMemorySize, A_SMEM);

    splitk<<<512, 256>>>(x, xh, xl, ELEM_X / 4);
    splitk<<<1024, 256>>>(y, yh, yl, ELEM_Y / 4);
    wtsk<<<dim3(16, 16, 1), dim3(32, 32)>>>(Wq, wh,            wl);
    wtsk<<<dim3(16, 16, 3), dim3(32, 32)>>>(Wk, wh + 1 * WSTR, wl + 1 * WSTR);
    wtsk<<<dim3(16, 16, 3), dim3(32, 32)>>>(Wv, wh + 4 * WSTR, wl + 4 * WSTR);
    wtsk<<<dim3(16, 16, 1), dim3(32, 32)>>>(Wp, wh + 7 * WSTR, wl + 7 * WSTR);

    dim3 gg(4, 32), gb(256);
    tgemm<1><<<gg, gb, GSM>>>(xh, xl, wh, wl, bq, nullptr, Qh, Ql, 0.125f);
    for (int i = 0; i < NSRC; i++) {
        size_t off = (size_t)i * 2 * 2048 * 512;
        tgemm<1><<<gg, gb, GSM>>>(yh + off, yl + off, wh + (1 + i) * WSTR, wl + (1 + i) * WSTR,
                                  bk + i * 512, nullptr, Kh + off, Kl + off, 1.0f);
        tgemm<2><<<gg, gb, GSM>>>(yh + off, yl + off, wh + (4 + i) * WSTR, wl + (4 + i) * WSTR,
                                  bv + i * 512, nullptr, Vth + off, Vtl + off, 1.0f);
    }
    attn<<<dim3(16, 8, 2), gb, A_SMEM>>>(Qh, Ql, Kh, Kl, Vth, Vtl, Oh, Ol);
    tgemm<0><<<gg, gb, GSM>>>(Oh, Ol, wh + 7 * WSTR, wl + 7 * WSTR, bp, out, nullptr, nullptr, 1.0f);
}

// round 11
// speedup vs baseline: 6.7364x; 1.0857x over previous
#include <cuda_runtime.h>
#include <cuda_bf16.h>
#include <stdint.h>

#define NSRC 3
#define ELEM_X (2*2048*512)
#define ELEM_Y (3*2*2048*512)
#define WSTR   (512*512)

__device__ __nv_bfloat16 g_xh[ELEM_X], g_xl[ELEM_X];
__device__ __nv_bfloat16 g_yh[ELEM_Y], g_yl[ELEM_Y];
__device__ __nv_bfloat16 g_wh[8*WSTR], g_wl[8*WSTR];
__device__ __nv_bfloat16 g_qh[ELEM_X], g_ql[ELEM_X];
__device__ __nv_bfloat16 g_kh[ELEM_Y], g_kl[ELEM_Y];
__device__ __nv_bfloat16 g_vth[ELEM_Y], g_vtl[ELEM_Y];   // V^T: [src*512+n][4096]
__device__ __nv_bfloat16 g_oh[ELEM_X], g_ol[ELEM_X];

#define SWZ(o) ((uint32_t)(o) ^ ((((uint32_t)(o)) >> 3) & 0x70u))
#define ID_128 0x8200490u   /* kind::f16 f32acc bf16 M=128 N=128 */
#define ID_PV  0x8100490u   /* kind::f16 f32acc bf16 M=128 N=64  */

#if defined(__CUDA_ARCH_FEAT_SM103_ALL) || defined(__CUDA_ARCH_FEAT_SM100_ALL) || !defined(__CUDA_ARCH__)
#define HAS_TC5 1
#else
#define HAS_TC5 0
#endif

__device__ __forceinline__ uint32_t elect1() {
    uint32_t p;
    asm volatile("{\n\t.reg .pred p;\n\telect.sync _|p, 0xFFFFFFFF;\n\tselp.b32 %0,1,0,p;\n\t}" : "=r"(p));
    return p;
}
__device__ __forceinline__ uint32_t s2u(const void* p) {
    uint32_t a;
    asm("{ .reg .u64 t; cvta.to.shared.u64 t, %1; cvt.u32.u64 %0, t; }" : "=r"(a) : "l"(p));
    return a;
}
__device__ __forceinline__ uint64_t dk(uint32_t a) {
    return (2ull<<61)|(1ull<<46)|(64ull<<32)|(1ull<<16)|((uint64_t)(a>>4)&0x3FFFull);
}

#define MBAR_INIT(a,n) asm volatile("mbarrier.init.shared.b64 [%0], %1;" :: "r"(a), "r"(n) : "memory")
#define MBAR_WAIT(a,ph) asm volatile("{\n\t.reg .pred P1;\n\tLW%=:\n\t" \
    "mbarrier.try_wait.parity.acquire.cta.shared::cta.b64 P1, [%0], %1, 0x989680;\n\t" \
    "@P1 bra.uni LD%=;\n\tbra.uni LW%=;\n\tLD%=:\n\t}" :: "r"(a), "r"(ph) : "memory")
#define FPROXY()       asm volatile("fence.proxy.async.shared::cta;" ::: "memory")
#define CPA16(d,s)     asm volatile("cp.async.cg.shared.global [%0], [%1], 16;" :: "r"(d), "l"(s))
#define CPA_COMMIT()   asm volatile("cp.async.commit_group;" ::: "memory")
#define CPA_WAIT0()    asm volatile("cp.async.wait_group 0;" ::: "memory")
#define CPA_WAIT1()    asm volatile("cp.async.wait_group 1;" ::: "memory")
#define CPA_WAIT2()    asm volatile("cp.async.wait_group 2;" ::: "memory")
#define CPA_MBAR(a)    asm volatile("cp.async.mbarrier.arrive.noinc.shared::cta.b64 [%0];" :: "r"(a) : "memory")

#if HAS_TC5
__device__ __forceinline__ void mma16(uint32_t d, uint64_t a, uint64_t b, uint32_t id, uint32_t acc) {
    asm volatile("{\n\t.reg .pred p;\n\tsetp.ne.u32 p, %4, 0;\n\t"
        "tcgen05.mma.cta_group::1.kind::f16 [%0], %1, %2, %3, {%5,%5,%5,%5}, p;\n\t}"
        :: "r"(d), "l"(a), "l"(b), "r"(id), "r"(acc), "r"(0u) : "memory");
}
#define TC_ALLOC(a,n)  asm volatile("tcgen05.alloc.cta_group::1.sync.aligned.shared::cta.b32 [%0], %1;" :: "r"(a), "r"(n) : "memory")
#define TC_RELQ()      asm volatile("tcgen05.relinquish_alloc_permit.cta_group::1.sync.aligned;")
#define TC_DEALLOC(t,n) asm volatile("tcgen05.dealloc.cta_group::1.sync.aligned.b32 %0, %1;" :: "r"(t), "r"(n))
#define TC_COMMIT(a)   asm volatile("tcgen05.commit.cta_group::1.mbarrier::arrive::one.shared::cluster.b64 [%0];" :: "r"(a) : "memory")
#define TC_FA()        asm volatile("tcgen05.fence::after_thread_sync;" ::: "memory")
#define TC_FB()        asm volatile("tcgen05.fence::before_thread_sync;" ::: "memory")
#define TC_WLD()       asm volatile("tcgen05.wait::ld.sync.aligned;" ::: "memory")
#define LDTM32(r, a) asm volatile( \
    "tcgen05.ld.sync.aligned.32x32b.x32.b32 " \
    "{%0,%1,%2,%3,%4,%5,%6,%7,%8,%9,%10,%11,%12,%13,%14,%15," \
    "%16,%17,%18,%19,%20,%21,%22,%23,%24,%25,%26,%27,%28,%29,%30,%31}, [%32];" \
    : "=r"((r)[0]),"=r"((r)[1]),"=r"((r)[2]),"=r"((r)[3]),"=r"((r)[4]),"=r"((r)[5]),"=r"((r)[6]),"=r"((r)[7]), \
      "=r"((r)[8]),"=r"((r)[9]),"=r"((r)[10]),"=r"((r)[11]),"=r"((r)[12]),"=r"((r)[13]),"=r"((r)[14]),"=r"((r)[15]), \
      "=r"((r)[16]),"=r"((r)[17]),"=r"((r)[18]),"=r"((r)[19]),"=r"((r)[20]),"=r"((r)[21]),"=r"((r)[22]),"=r"((r)[23]), \
      "=r"((r)[24]),"=r"((r)[25]),"=r"((r)[26]),"=r"((r)[27]),"=r"((r)[28]),"=r"((r)[29]),"=r"((r)[30]),"=r"((r)[31]) \
    : "r"(a))
#else
__device__ __forceinline__ void mma16(uint32_t, uint64_t, uint64_t, uint32_t, uint32_t) { __trap(); }
#define TC_ALLOC(a,n)   __trap()
#define TC_RELQ()       __trap()
#define TC_DEALLOC(t,n) __trap()
#define TC_COMMIT(a)    __trap()
#define TC_FA()         ((void)0)
#define TC_FB()         ((void)0)
#define TC_WLD()        ((void)0)
#define LDTM32(r, a) do { _Pragma("unroll") for (int _i = 0; _i < 32; _i++) (r)[_i] = 0u; __trap(); } while (0)
#endif

__device__ __forceinline__ uint32_t packh(__nv_bfloat16 a, __nv_bfloat16 b) {
    __nv_bfloat162 v; v.x = a; v.y = b;
    return *reinterpret_cast<uint32_t*>(&v);
}
__device__ __forceinline__ uint32_t pack2(float lo, float hi) {
    uint32_t r;
    asm("cvt.rn.bf16x2.f32 %0, %1, %2;" : "=r"(r) : "f"(hi), "f"(lo));
    return r;
}

// ------------------------- prep kernels -----------------------------------
__global__ void splitk(const float* __restrict__ in, __nv_bfloat16* __restrict__ oh,
                       __nv_bfloat16* __restrict__ ol, int n4) {
    for (int i = blockIdx.x * blockDim.x + threadIdx.x; i < n4; i += gridDim.x * blockDim.x) {
        float4 v = ((const float4*)in)[i];
        __nv_bfloat16 h0 = __float2bfloat16_rn(v.x), h1 = __float2bfloat16_rn(v.y);
        __nv_bfloat16 h2 = __float2bfloat16_rn(v.z), h3 = __float2bfloat16_rn(v.w);
        __nv_bfloat16 l0 = __float2bfloat16_rn(v.x - __bfloat162float(h0));
        __nv_bfloat16 l1 = __float2bfloat16_rn(v.y - __bfloat162float(h1));
        __nv_bfloat16 l2 = __float2bfloat16_rn(v.z - __bfloat162float(h2));
        __nv_bfloat16 l3 = __float2bfloat16_rn(v.w - __bfloat162float(h3));
        *(uint2*)(oh + 4 * (size_t)i) = make_uint2(packh(h0, h1), packh(h2, h3));
        *(uint2*)(ol + 4 * (size_t)i) = make_uint2(packh(l0, l1), packh(l2, l3));
    }
}

__global__ void wtsk(const float* __restrict__ W, __nv_bfloat16* __restrict__ th,
                     __nv_bfloat16* __restrict__ tl) {
    __shared__ float t[32][33];
    int m = blockIdx.z;
    int k0 = blockIdx.x * 32, n0 = blockIdx.y * 32;
    const float* Wm = W + (size_t)m * WSTR;
    t[threadIdx.y][threadIdx.x] = Wm[(size_t)(k0 + threadIdx.y) * 512 + n0 + threadIdx.x];
    __syncthreads();
    float v = t[threadIdx.x][threadIdx.y];
    size_t di = (size_t)m * WSTR + (size_t)(n0 + threadIdx.y) * 512 + k0 + threadIdx.x;
    __nv_bfloat16 h = __float2bfloat16_rn(v);
    th[di] = h;
    tl[di] = __float2bfloat16_rn(v - __bfloat162float(h));
}

// ------------------------- tcgen05 GEMM (triple-buffered cp.async) ---------
template <int MODE>
__global__ __launch_bounds__(256) void tgemm(
    const __nv_bfloat16* __restrict__ ah, const __nv_bfloat16* __restrict__ al,
    const __nv_bfloat16* __restrict__ bh, const __nv_bfloat16* __restrict__ bl,
    const float* __restrict__ bias, float* __restrict__ of,
    __nv_bfloat16* __restrict__ oh, __nv_bfloat16* __restrict__ ol, float scale)
{
    extern __shared__ char sm[];
    const uint32_t sb = s2u(sm);
    const int tid = threadIdx.x, wid = tid >> 5, lane = tid & 31;
    const int bm = blockIdx.y * 128, bn = blockIdx.x * 128;

    if (wid == 0) { TC_ALLOC(sb, 128); TC_RELQ(); }
    if (tid == 0) MBAR_INIT(sb + 8, 1);
    __syncthreads();
    uint32_t tm;
    asm volatile("ld.shared.b32 %0, [%1];" : "=r"(tm) : "r"(sb));

    auto stage = [&](int kc, int buf) {
#pragma unroll
        for (int i = 0; i < 16; i++) {
            int idx = tid + i * 256;
            int t = idx >> 10, r = (idx >> 3) & 127, u = idx & 7;
            const __nv_bfloat16* src = (t == 0) ? ah : (t == 1) ? al : (t == 2) ? bh : bl;
            int grow = ((t < 2) ? bm : bn) + r;
            CPA16(sb + 1024 + buf * 65536 + t * 16384 + SWZ(r * 128 + u * 16),
                  src + (size_t)grow * 512 + kc * 64 + u * 8);
        }
        CPA_COMMIT();
    };

    stage(0, 0);
    stage(1, 1);
    for (int kc = 0; kc < 8; kc++) {
        int buf = kc % 3;
        if (kc >= 1) MBAR_WAIT(sb + 8, (kc - 1) & 1);
        if (kc + 2 < 8) stage(kc + 2, (kc + 2) % 3);
        if (kc < 6) CPA_WAIT2(); else if (kc == 6) CPA_WAIT1(); else CPA_WAIT0();
        FPROXY(); __syncthreads();
        if (wid == 0 && elect1()) {
            uint32_t ab = sb + 1024 + buf * 65536;
            uint64_t dah = dk(ab), dal = dk(ab + 16384);
            uint64_t dbh = dk(ab + 32768), dbl = dk(ab + 49152);
#pragma unroll
            for (int s = 0; s < 4; s++) mma16(tm, dah + 2*s, dbh + 2*s, ID_128, (kc > 0) || (s > 0));
#pragma unroll
            for (int s = 0; s < 4; s++) mma16(tm, dah + 2*s, dbl + 2*s, ID_128, 1);
#pragma unroll
            for (int s = 0; s < 4; s++) mma16(tm, dal + 2*s, dbh + 2*s, ID_128, 1);
            TC_COMMIT(sb + 8);
        }
    }
    MBAR_WAIT(sb + 8, 1);
    TC_FA();

    const int r = (wid & 3) * 32 + lane, cb = (wid >> 2) * 64;
    uint32_t u[64];
    LDTM32(u, tm + cb);
    LDTM32(u + 32, tm + cb + 32);
    TC_WLD(); TC_FB();
    float f[64];
#pragma unroll
    for (int j = 0; j < 64; j++)
        f[j] = scale * (__uint_as_float(u[j]) + bias[bn + cb + j]);
    if (MODE == 0) {
        float* p = of + (size_t)(bm + r) * 512 + bn + cb;
#pragma unroll
        for (int g = 0; g < 16; g++)
            *(float4*)(p + g * 4) = make_float4(f[g*4], f[g*4+1], f[g*4+2], f[g*4+3]);
    } else if (MODE == 1) {
        uint32_t hw[32], lw[32];
#pragma unroll
        for (int j = 0; j < 32; j++) {
            __nv_bfloat16 h0 = __float2bfloat16_rn(f[2*j]), h1 = __float2bfloat16_rn(f[2*j+1]);
            hw[j] = packh(h0, h1);
            lw[j] = packh(__float2bfloat16_rn(f[2*j]   - __bfloat162float(h0)),
                          __float2bfloat16_rn(f[2*j+1] - __bfloat162float(h1)));
        }
        size_t o = (size_t)(bm + r) * 512 + bn + cb;
#pragma unroll
        for (int g = 0; g < 8; g++) {
            *(uint4*)(oh + o + g * 8) = make_uint4(hw[g*4], hw[g*4+1], hw[g*4+2], hw[g*4+3]);
            *(uint4*)(ol + o + g * 8) = make_uint4(lw[g*4], lw[g*4+1], lw[g*4+2], lw[g*4+3]);
        }
    } else {
#pragma unroll
        for (int j = 0; j < 64; j++) {
            __nv_bfloat16 h0 = __float2bfloat16_rn(f[j]);
            __nv_bfloat16 l0 = __float2bfloat16_rn(f[j] - __bfloat162float(h0));
            size_t o = (size_t)(bn + cb + j) * 4096 + bm + r;
            oh[o] = h0;
            ol[o] = l0;
        }
    }
    __syncthreads();
    if (wid == 0) TC_DEALLOC(tm, 128);
}
#define GSM (1024 + 3 * 65536)

// ------------------------- pipelined tcgen05 attention ---------------------
// mbars: s=8, pv=16, kf0=24, kf1=32, vf0=40, vf1=48 (kf/vf count=256, noinc arrives)
#define A_Q   2048
#define A_K0  34816
#define A_V0  100352
#define A_PH  165888
#define A_PL  198656
#define A_SMEM 231424
#define NT 48

__global__ __launch_bounds__(256) void attn(
    const __nv_bfloat16* __restrict__ qh, const __nv_bfloat16* __restrict__ ql,
    const __nv_bfloat16* __restrict__ kh, const __nv_bfloat16* __restrict__ kl,
    const __nv_bfloat16* __restrict__ vth, const __nv_bfloat16* __restrict__ vtl,
    __nv_bfloat16* __restrict__ oh, __nv_bfloat16* __restrict__ ol)
{
    extern __shared__ char sm[];
    const uint32_t sb = s2u(sm);
    float* lsumf = (float*)(sm + 64);
    const int tid = threadIdx.x, wid = tid >> 5, lane = tid & 31;
    const int q0 = blockIdx.x * 128, h = blockIdx.y, b = blockIdx.z;

    if (wid == 0) { TC_ALLOC(sb, 512); TC_RELQ(); }
    if (tid == 0) {
        MBAR_INIT(sb + 8, 1);  MBAR_INIT(sb + 16, 1);
        MBAR_INIT(sb + 24, 256); MBAR_INIT(sb + 32, 256);
        MBAR_INIT(sb + 40, 256); MBAR_INIT(sb + 48, 256);
    }
    if (tid < 128) { lsumf[tid] = 0.f; lsumf[128 + tid] = 0.f; lsumf[256 + tid] = 0.f; }
    __syncthreads();
    uint32_t tm;
    asm volatile("ld.shared.b32 %0, [%1];" : "=r"(tm) : "r"(sb));
    const uint32_t tmo = tm + 256;

    auto ldK = [&](int g1, int buf) {       // 8 cp.async/thread -> kf[buf]
        int srcI = g1 >> 4, kt = g1 & 15;
        const size_t kvb = ((size_t)(srcI * 2 + b)) * 2048 * 512 + h * 64;
        uint32_t base = sb + A_K0 + buf * 32768;
#pragma unroll
        for (int i = 0; i < 8; i++) {
            int idx = tid + i * 256;
            int mat = idx >> 10, rem = idx & 1023;
            int rr = rem >> 3, u = rem & 7;
            const __nv_bfloat16* s0 = mat ? kl : kh;
            CPA16(base + mat * 16384 + SWZ(rr * 128 + u * 16),
                  s0 + kvb + (size_t)(kt * 128 + rr) * 512 + u * 8);
        }
        CPA_MBAR(sb + 24 + buf * 8);
    };
    auto ldV = [&](int g1, int buf) {       // 8 cp.async/thread -> vf[buf]
        int srcI = g1 >> 4, kt = g1 & 15;
        const size_t vtb = ((size_t)(srcI * 512 + h * 64)) * 4096 + b * 2048;
        uint32_t base = sb + A_V0 + buf * 32768;
#pragma unroll
        for (int i = 0; i < 8; i++) {
            int idx = tid + i * 256;
            int mat = idx >> 10, rem = idx & 1023;
            int d = rem >> 4, u = rem & 15;
            const __nv_bfloat16* s0 = mat ? vtl : vth;
            CPA16(base + mat * 16384 + (u >> 3) * 8192 + SWZ(d * 128 + (u & 7) * 16),
                  s0 + vtb + (size_t)d * 4096 + kt * 128 + u * 8);
        }
        CPA_MBAR(sb + 40 + buf * 8);
    };

    // Q tile hi/lo (once, regular stores)
#pragma unroll
    for (int i = 0; i < 8; i++) {
        int idx = tid + i * 256;
        int t = idx >> 10, r = (idx >> 3) & 127, u = idx & 7;
        const __nv_bfloat16* src = t ? ql : qh;
        uint4 v = *(const uint4*)(src + (size_t)(b * 2048 + q0 + r) * 512 + h * 64 + u * 8);
        *(uint4*)(sm + A_Q + t * 16384 + SWZ(r * 128 + u * 16)) = v;
    }

    // prologue: K(0),V(0),K(1) staged; S(0) issued once K(0) lands
    ldK(0, 0); ldV(0, 0); ldK(1, 1);
    FPROXY(); __syncthreads();
    if (wid == 0 && elect1()) {
        MBAR_WAIT(sb + 24, 0);            // kf0 phase 0
        FPROXY();
        uint64_t dqh = dk(sb + A_Q), dql = dk(sb + A_Q + 16384);
        uint64_t dkh = dk(sb + A_K0), dkl = dk(sb + A_K0 + 16384);
#pragma unroll
        for (int s = 0; s < 4; s++) mma16(tm, dqh + 2*s, dkh + 2*s, ID_128, s > 0);
#pragma unroll
        for (int s = 0; s < 4; s++) mma16(tm, dqh + 2*s, dkl + 2*s, ID_128, 1);
#pragma unroll
        for (int s = 0; s < 4; s++) mma16(tm, dql + 2*s, dkh + 2*s, ID_128, 1);
        TC_COMMIT(sb + 8);
    }

    const int r = (wid & 3) * 32 + lane;
    const int cb = (wid >> 2) * 64;
    const int cb2 = (wid >> 2) * 32;

    for (int g = 0; g < NT; g++) {
        const int srcI = g >> 4;
        MBAR_WAIT(sb + 8, g & 1);                     // S(g) done
        TC_FA();
        if (g + 2 < NT) ldK(g + 2, g & 1);            // K buf freed by S(g)

        if (g + 1 < NT && wid == 0 && elect1()) {     // S(g+1) at iteration top
            MBAR_WAIT(sb + 24 + ((g + 1) & 1) * 8, ((g + 1) >> 1) & 1);
            FPROXY();
            uint32_t kb = sb + A_K0 + ((g + 1) & 1) * 32768;
            uint64_t dqh = dk(sb + A_Q), dql = dk(sb + A_Q + 16384);
            uint64_t dkh = dk(kb), dkl = dk(kb + 16384);
            uint32_t tms = tm + ((g + 1) & 1) * 128;
#pragma unroll
            for (int s = 0; s < 4; s++) mma16(tms, dqh + 2*s, dkh + 2*s, ID_128, s > 0);
#pragma unroll
            for (int s = 0; s < 4; s++) mma16(tms, dqh + 2*s, dkl + 2*s, ID_128, 1);
#pragma unroll
            for (int s = 0; s < 4; s++) mma16(tms, dql + 2*s, dkh + 2*s, ID_128, 1);
            TC_COMMIT(sb + 8);
        }

        uint32_t u0[64];
        float ps = 0.0f;
        LDTM32(u0, tm + (g & 1) * 128 + cb);
        TC_WLD();
        LDTM32(u0 + 32, tm + (g & 1) * 128 + cb + 32);  // overlaps exp chunk A
#pragma unroll
        for (int j = 0; j < 16; j++) {                   // exp chunk A
            float e0 = __expf(__uint_as_float(u0[2*j]));
            float e1 = __expf(__uint_as_float(u0[2*j + 1]));
            ps += e0 + e1;
            uint32_t hw = pack2(e0, e1);
            float h0 = __uint_as_float(hw << 16);
            float h1 = __uint_as_float(hw & 0xffff0000u);
            u0[2*j]     = hw;
            u0[2*j + 1] = pack2(e0 - h0, e1 - h1);
        }
        TC_WLD(); TC_FB();
#pragma unroll
        for (int j = 16; j < 32; j++) {                  // exp chunk B
            float e0 = __expf(__uint_as_float(u0[2*j]));
            float e1 = __expf(__uint_as_float(u0[2*j + 1]));
            ps += e0 + e1;
            uint32_t hw = pack2(e0, e1);
            float h0 = __uint_as_float(hw << 16);
            float h1 = __uint_as_float(hw & 0xffff0000u);
            u0[2*j]     = hw;
            u0[2*j + 1] = pack2(e0 - h0, e1 - h1);
        }

        if (g >= 1) MBAR_WAIT(sb + 16, (g - 1) & 1);   // PV(g-1): P + V(g-1) buf free
        if (g + 1 < NT) ldV(g + 1, (g + 1) & 1);

#pragma unroll
        for (int j4 = 0; j4 < 16; j4++) {
            int t = cb + j4 * 4;
            uint32_t off = (uint32_t)((t >> 6) * 16384) + SWZ(r * 128 + (t & 63) * 2);
            *(uint2*)(sm + A_PH + off) = make_uint2(u0[j4*4],     u0[j4*4 + 2]);
            *(uint2*)(sm + A_PL + off) = make_uint2(u0[j4*4 + 1], u0[j4*4 + 3]);
        }
        atomicAdd(&lsumf[srcI * 128 + r], ps);
        FPROXY(); __syncthreads();                     // P visible to all

        if (wid == 0 && elect1()) {                    // PV(g)
            MBAR_WAIT(sb + 40 + (g & 1) * 8, (g >> 1) & 1);   // V(g) resident
            FPROXY();
            uint32_t vb0 = sb + A_V0 + (g & 1) * 32768;
            uint64_t dph = dk(sb + A_PH), dpl = dk(sb + A_PL);
            uint64_t dvh = dk(vb0), dvl = dk(vb0 + 16384);
            uint32_t dsto = tmo + srcI * 64;
            int accbase = (g & 15) > 0;
#pragma unroll
            for (int s = 0; s < 8; s++) {
                uint64_t pa = (uint64_t)((s >> 2) * 1024 + (s & 3) * 2);
                uint64_t vb = (uint64_t)((s >> 2) * 512  + (s & 3) * 2);
                mma16(dsto, dph + pa, dvh + vb, ID_PV, accbase || (s > 0));
            }
#pragma unroll
            for (int s = 0; s < 8; s++) {
                uint64_t pa = (uint64_t)((s >> 2) * 1024 + (s & 3) * 2);
                uint64_t vb = (uint64_t)((s >> 2) * 512  + (s & 3) * 2);
                mma16(dsto, dph + pa, dvl + vb, ID_PV, 1);
            }
#pragma unroll
            for (int s = 0; s < 8; s++) {
                uint64_t pa = (uint64_t)((s >> 2) * 1024 + (s & 3) * 2);
                uint64_t vb = (uint64_t)((s >> 2) * 512  + (s & 3) * 2);
                mma16(dsto, dpl + pa, dvh + vb, ID_PV, 1);
            }
            TC_COMMIT(sb + 16);
        }
    }

    MBAR_WAIT(sb + 16, (NT - 1) & 1);   // PV(47)
    TC_FA();
    __syncthreads();

    float oacc[32];
#pragma unroll
    for (int j = 0; j < 32; j++) oacc[j] = 0.0f;
#pragma unroll
    for (int srcI = 0; srcI < 3; srcI++) {
        uint32_t uo[32];
        LDTM32(uo, tmo + srcI * 64 + cb2);
        TC_WLD();
        float inv = 1.0f / lsumf[srcI * 128 + r];
#pragma unroll
        for (int j = 0; j < 32; j++) oacc[j] += __uint_as_float(uo[j]) * inv;
    }
    TC_FB();

    uint32_t hw[16], lw[16];
#pragma unroll
    for (int j = 0; j < 16; j++) {
        __nv_bfloat16 h0 = __float2bfloat16_rn(oacc[2*j]), h1 = __float2bfloat16_rn(oacc[2*j+1]);
        hw[j] = packh(h0, h1);
        lw[j] = packh(__float2bfloat16_rn(oacc[2*j]   - __bfloat162float(h0)),
                      __float2bfloat16_rn(oacc[2*j+1] - __bfloat162float(h1)));
    }
    size_t o = (size_t)(b * 2048 + q0 + r) * 512 + h * 64 + cb2;
#pragma unroll
    for (int g2 = 0; g2 < 4; g2++) {
        *(uint4*)(oh + o + g2 * 8) = make_uint4(hw[g2*4], hw[g2*4+1], hw[g2*4+2], hw[g2*4+3]);
        *(uint4*)(ol + o + g2 * 8) = make_uint4(lw[g2*4], lw[g2*4+1], lw[g2*4+2], lw[g2*4+3]);
    }
    __syncthreads();
    if (wid == 0) TC_DEALLOC(tm, 512);
}

// ---------------------------------------------------------------------------
extern "C" void kernel_launch(void* const* d_in, const int* in_sizes, int n_in,
                              void* d_out, int out_size)
{
    const float* x  = (const float*)d_in[0];
    const float* y  = (const float*)d_in[1];
    const float* Wq = (const float*)d_in[2];
    const float* bq = (const float*)d_in[3];
    const float* Wk = (const float*)d_in[4];
    const float* bk = (const float*)d_in[5];
    const float* Wv = (const float*)d_in[6];
    const float* bv = (const float*)d_in[7];
    const float* Wp = (const float*)d_in[8];
    const float* bp = (const float*)d_in[9];
    float* out = (float*)d_out;

    __nv_bfloat16 *xh, *xl, *yh, *yl, *wh, *wl, *Qh, *Ql, *Kh, *Kl, *Vth, *Vtl, *Oh, *Ol;
    cudaGetSymbolAddress((void**)&xh, g_xh);  cudaGetSymbolAddress((void**)&xl, g_xl);
    cudaGetSymbolAddress((void**)&yh, g_yh);  cudaGetSymbolAddress((void**)&yl, g_yl);
    cudaGetSymbolAddress((void**)&wh, g_wh);  cudaGetSymbolAddress((void**)&wl, g_wl);
    cudaGetSymbolAddress((void**)&Qh, g_qh);  cudaGetSymbolAddress((void**)&Ql, g_ql);
    cudaGetSymbolAddress((void**)&Kh, g_kh);  cudaGetSymbolAddress((void**)&Kl, g_kl);
    cudaGetSymbolAddress((void**)&Vth, g_vth); cudaGetSymbolAddress((void**)&Vtl, g_vtl);
    cudaGetSymbolAddress((void**)&Oh, g_oh);  cudaGetSymbolAddress((void**)&Ol, g_ol);

    cudaFuncSetAttribute(tgemm<0>, cudaFuncAttributeMaxDynamicSharedMemorySize, GSM);
    cudaFuncSetAttribute(tgemm<1>, cudaFuncAttributeMaxDynamicSharedMemorySize, GSM);
    cudaFuncSetAttribute(tgemm<2>, cudaFuncAttributeMaxDynamicSharedMemorySize, GSM);
    cudaFuncSetAttribute(attn,     cudaFuncAttributeMaxDynamicSharedMemorySize, A_SMEM);

    splitk<<<512, 256>>>(x, xh, xl, ELEM_X / 4);
    splitk<<<1024, 256>>>(y, yh, yl, ELEM_Y / 4);
    wtsk<<<dim3(16, 16, 1), dim3(32, 32)>>>(Wq, wh,            wl);
    wtsk<<<dim3(16, 16, 3), dim3(32, 32)>>>(Wk, wh + 1 * WSTR, wl + 1 * WSTR);
    wtsk<<<dim3(16, 16, 3), dim3(32, 32)>>>(Wv, wh + 4 * WSTR, wl + 4 * WSTR);
    wtsk<<<dim3(16, 16, 1), dim3(32, 32)>>>(Wp, wh + 7 * WSTR, wl + 7 * WSTR);

    dim3 gg(4, 32), gb(256);
    tgemm<1><<<gg, gb, GSM>>>(xh, xl, wh, wl, bq, nullptr, Qh, Ql, 0.125f);
    for (int i = 0; i < NSRC; i++) {
        size_t off = (size_t)i * 2 * 2048 * 512;
        tgemm<1><<<gg, gb, GSM>>>(yh + off, yl + off, wh + (1 + i) * WSTR, wl + (1 + i) * WSTR,
                                  bk + i * 512, nullptr, Kh + off, Kl + off, 1.0f);
        tgemm<2><<<gg, gb, GSM>>>(yh + off, yl + off, wh + (4 + i) * WSTR, wl + (4 + i) * WSTR,
                                  bv + i * 512, nullptr, Vth + off, Vtl + off, 1.0f);
    }
    attn<<<dim3(16, 8, 2), gb, A_SMEM>>>(Qh, Ql, Kh, Kl, Vth, Vtl, Oh, Ol);
    tgemm<0><<<gg, gb, GSM>>>(Oh, Ol, wh + 7 * WSTR, wl + 7 * WSTR, bp, out, nullptr, nullptr, 1.0f);
}

// round 13
// speedup vs baseline: 7.5515x; 1.1210x over previous
#include <cuda_runtime.h>
#include <cuda_bf16.h>
#include <stdint.h>

#define NSRC 3
#define ELEM_X (2*2048*512)
#define ELEM_Y (3*2*2048*512)
#define WSTR   (512*512)

__device__ __nv_bfloat16 g_xh[ELEM_X], g_xl[ELEM_X];
__device__ __nv_bfloat16 g_yh[ELEM_Y], g_yl[ELEM_Y];
__device__ __nv_bfloat16 g_wh[8*WSTR], g_wl[8*WSTR];
__device__ __nv_bfloat16 g_qh[ELEM_X], g_ql[ELEM_X];
__device__ __nv_bfloat16 g_kh[ELEM_Y], g_kl[ELEM_Y];
__device__ __nv_bfloat16 g_vth[ELEM_Y], g_vtl[ELEM_Y];   // V^T: [src*512+n][4096]
__device__ __nv_bfloat16 g_oh[ELEM_X], g_ol[ELEM_X];

#define SWZ(o) ((uint32_t)(o) ^ ((((uint32_t)(o)) >> 3) & 0x70u))
#define ID_128 0x8200490u   /* kind::f16 f32acc bf16 M=128 N=128 */
#define ID_PV  0x8100490u   /* kind::f16 f32acc bf16 M=128 N=64  */

#if defined(__CUDA_ARCH_FEAT_SM103_ALL) || defined(__CUDA_ARCH_FEAT_SM100_ALL) || !defined(__CUDA_ARCH__)
#define HAS_TC5 1
#else
#define HAS_TC5 0
#endif

__device__ __forceinline__ uint32_t elect1() {
    uint32_t p;
    asm volatile("{\n\t.reg .pred p;\n\telect.sync _|p, 0xFFFFFFFF;\n\tselp.b32 %0,1,0,p;\n\t}" : "=r"(p));
    return p;
}
__device__ __forceinline__ uint32_t s2u(const void* p) {
    uint32_t a;
    asm("{ .reg .u64 t; cvta.to.shared.u64 t, %1; cvt.u32.u64 %0, t; }" : "=r"(a) : "l"(p));
    return a;
}
__device__ __forceinline__ uint64_t dk(uint32_t a) {
    return (2ull<<61)|(1ull<<46)|(64ull<<32)|(1ull<<16)|((uint64_t)(a>>4)&0x3FFFull);
}

#define MBAR_INIT(a,n) asm volatile("mbarrier.init.shared.b64 [%0], %1;" :: "r"(a), "r"(n) : "memory")
#define MBAR_WAIT(a,ph) asm volatile("{\n\t.reg .pred P1;\n\tLW%=:\n\t" \
    "mbarrier.try_wait.parity.acquire.cta.shared::cta.b64 P1, [%0], %1, 0x989680;\n\t" \
    "@P1 bra.uni LD%=;\n\tbra.uni LW%=;\n\tLD%=:\n\t}" :: "r"(a), "r"(ph) : "memory")
#define FPROXY()       asm volatile("fence.proxy.async.shared::cta;" ::: "memory")
#define CPA16(d,s)     asm volatile("cp.async.cg.shared.global [%0], [%1], 16;" :: "r"(d), "l"(s))
#define CPA_COMMIT()   asm volatile("cp.async.commit_group;" ::: "memory")
#define CPA_WAIT0()    asm volatile("cp.async.wait_group 0;" ::: "memory")
#define CPA_WAIT1()    asm volatile("cp.async.wait_group 1;" ::: "memory")
#define CPA_WAIT2()    asm volatile("cp.async.wait_group 2;" ::: "memory")
#define CPA_MBAR(a)    asm volatile("cp.async.mbarrier.arrive.noinc.shared::cta.b64 [%0];" :: "r"(a) : "memory")

#if HAS_TC5
__device__ __forceinline__ void mma16(uint32_t d, uint64_t a, uint64_t b, uint32_t id, uint32_t acc) {
    asm volatile("{\n\t.reg .pred p;\n\tsetp.ne.u32 p, %4, 0;\n\t"
        "tcgen05.mma.cta_group::1.kind::f16 [%0], %1, %2, %3, {%5,%5,%5,%5}, p;\n\t}"
        :: "r"(d), "l"(a), "l"(b), "r"(id), "r"(acc), "r"(0u) : "memory");
}
#define TC_ALLOC(a,n)  asm volatile("tcgen05.alloc.cta_group::1.sync.aligned.shared::cta.b32 [%0], %1;" :: "r"(a), "r"(n) : "memory")
#define TC_RELQ()      asm volatile("tcgen05.relinquish_alloc_permit.cta_group::1.sync.aligned;")
#define TC_DEALLOC(t,n) asm volatile("tcgen05.dealloc.cta_group::1.sync.aligned.b32 %0, %1;" :: "r"(t), "r"(n))
#define TC_COMMIT(a)   asm volatile("tcgen05.commit.cta_group::1.mbarrier::arrive::one.shared::cluster.b64 [%0];" :: "r"(a) : "memory")
#define TC_FA()        asm volatile("tcgen05.fence::after_thread_sync;" ::: "memory")
#define TC_FB()        asm volatile("tcgen05.fence::before_thread_sync;" ::: "memory")
#define TC_WLD()       asm volatile("tcgen05.wait::ld.sync.aligned;" ::: "memory")
#define LDTM32(r, a) asm volatile( \
    "tcgen05.ld.sync.aligned.32x32b.x32.b32 " \
    "{%0,%1,%2,%3,%4,%5,%6,%7,%8,%9,%10,%11,%12,%13,%14,%15," \
    "%16,%17,%18,%19,%20,%21,%22,%23,%24,%25,%26,%27,%28,%29,%30,%31}, [%32];" \
    : "=r"((r)[0]),"=r"((r)[1]),"=r"((r)[2]),"=r"((r)[3]),"=r"((r)[4]),"=r"((r)[5]),"=r"((r)[6]),"=r"((r)[7]), \
      "=r"((r)[8]),"=r"((r)[9]),"=r"((r)[10]),"=r"((r)[11]),"=r"((r)[12]),"=r"((r)[13]),"=r"((r)[14]),"=r"((r)[15]), \
      "=r"((r)[16]),"=r"((r)[17]),"=r"((r)[18]),"=r"((r)[19]),"=r"((r)[20]),"=r"((r)[21]),"=r"((r)[22]),"=r"((r)[23]), \
      "=r"((r)[24]),"=r"((r)[25]),"=r"((r)[26]),"=r"((r)[27]),"=r"((r)[28]),"=r"((r)[29]),"=r"((r)[30]),"=r"((r)[31]) \
    : "r"(a))
#else
__device__ __forceinline__ void mma16(uint32_t, uint64_t, uint64_t, uint32_t, uint32_t) { __trap(); }
#define TC_ALLOC(a,n)   __trap()
#define TC_RELQ()       __trap()
#define TC_DEALLOC(t,n) __trap()
#define TC_COMMIT(a)    __trap()
#define TC_FA()         ((void)0)
#define TC_FB()         ((void)0)
#define TC_WLD()        ((void)0)
#define LDTM32(r, a) do { _Pragma("unroll") for (int _i = 0; _i < 32; _i++) (r)[_i] = 0u; __trap(); } while (0)
#endif

__device__ __forceinline__ uint32_t packh(__nv_bfloat16 a, __nv_bfloat16 b) {
    __nv_bfloat162 v; v.x = a; v.y = b;
    return *reinterpret_cast<uint32_t*>(&v);
}
__device__ __forceinline__ uint32_t pack2(float lo, float hi) {
    uint32_t r;
    asm("cvt.rn.bf16x2.f32 %0, %1, %2;" : "=r"(r) : "f"(hi), "f"(lo));
    return r;
}

// ------------------------- prep kernels -----------------------------------
__global__ void splitk(const float* __restrict__ in, __nv_bfloat16* __restrict__ oh,
                       __nv_bfloat16* __restrict__ ol, int n4) {
    for (int i = blockIdx.x * blockDim.x + threadIdx.x; i < n4; i += gridDim.x * blockDim.x) {
        float4 v = ((const float4*)in)[i];
        __nv_bfloat16 h0 = __float2bfloat16_rn(v.x), h1 = __float2bfloat16_rn(v.y);
        __nv_bfloat16 h2 = __float2bfloat16_rn(v.z), h3 = __float2bfloat16_rn(v.w);
        __nv_bfloat16 l0 = __float2bfloat16_rn(v.x - __bfloat162float(h0));
        __nv_bfloat16 l1 = __float2bfloat16_rn(v.y - __bfloat162float(h1));
        __nv_bfloat16 l2 = __float2bfloat16_rn(v.z - __bfloat162float(h2));
        __nv_bfloat16 l3 = __float2bfloat16_rn(v.w - __bfloat162float(h3));
        *(uint2*)(oh + 4 * (size_t)i) = make_uint2(packh(h0, h1), packh(h2, h3));
        *(uint2*)(ol + 4 * (size_t)i) = make_uint2(packh(l0, l1), packh(l2, l3));
    }
}

__global__ void wtsk(const float* __restrict__ W, __nv_bfloat16* __restrict__ th,
                     __nv_bfloat16* __restrict__ tl) {
    __shared__ float t[32][33];
    int m = blockIdx.z;
    int k0 = blockIdx.x * 32, n0 = blockIdx.y * 32;
    const float* Wm = W + (size_t)m * WSTR;
    t[threadIdx.y][threadIdx.x] = Wm[(size_t)(k0 + threadIdx.y) * 512 + n0 + threadIdx.x];
    __syncthreads();
    float v = t[threadIdx.x][threadIdx.y];
    size_t di = (size_t)m * WSTR + (size_t)(n0 + threadIdx.y) * 512 + k0 + threadIdx.x;
    __nv_bfloat16 h = __float2bfloat16_rn(v);
    th[di] = h;
    tl[di] = __float2bfloat16_rn(v - __bfloat162float(h));
}

// ------------------------- unified projection GEMM -------------------------
// grid (4, 32, 7): z=0 Q (scale 1/8), z=1..3 K_i, z=4..6 V_i (transposed out).
__global__ __launch_bounds__(256) void proj(
    const __nv_bfloat16* __restrict__ xh, const __nv_bfloat16* __restrict__ xl,
    const __nv_bfloat16* __restrict__ yh, const __nv_bfloat16* __restrict__ yl,
    const __nv_bfloat16* __restrict__ wh, const __nv_bfloat16* __restrict__ wl,
    const float* __restrict__ bq, const float* __restrict__ bk, const float* __restrict__ bv,
    __nv_bfloat16* __restrict__ Qh, __nv_bfloat16* __restrict__ Ql,
    __nv_bfloat16* __restrict__ Kh, __nv_bfloat16* __restrict__ Kl,
    __nv_bfloat16* __restrict__ Vth, __nv_bfloat16* __restrict__ Vtl)
{
    extern __shared__ char sm[];
    const uint32_t sb = s2u(sm);
    const int tid = threadIdx.x, wid = tid >> 5, lane = tid & 31;
    const int bm = blockIdx.y * 128, bn = blockIdx.x * 128;
    const int z = blockIdx.z;

    const __nv_bfloat16 *ah, *al, *bhp, *blp;
    const float* bias;
    __nv_bfloat16 *ohp, *olp;
    float scale;
    int mode;   // 1 = row-major split out, 2 = transposed split out
    if (z == 0) {
        ah = xh; al = xl; bhp = wh; blp = wl; bias = bq;
        ohp = Qh; olp = Ql; scale = 0.125f; mode = 1;
    } else if (z <= 3) {
        int s = z - 1; size_t off = (size_t)s * 2 * 2048 * 512;
        ah = yh + off; al = yl + off;
        bhp = wh + (size_t)(1 + s) * WSTR; blp = wl + (size_t)(1 + s) * WSTR;
        bias = bk + 512 * s; ohp = Kh + off; olp = Kl + off; scale = 1.0f; mode = 1;
    } else {
        int s = z - 4; size_t off = (size_t)s * 2 * 2048 * 512;
        ah = yh + off; al = yl + off;
        bhp = wh + (size_t)(4 + s) * WSTR; blp = wl + (size_t)(4 + s) * WSTR;
        bias = bv + 512 * s; ohp = Vth + off; olp = Vtl + off; scale = 1.0f; mode = 2;
    }

    if (wid == 0) { TC_ALLOC(sb, 128); TC_RELQ(); }
    if (tid == 0) MBAR_INIT(sb + 8, 1);
    __syncthreads();
    uint32_t tm;
    asm volatile("ld.shared.b32 %0, [%1];" : "=r"(tm) : "r"(sb));

    auto stage = [&](int kc, int buf) {
#pragma unroll
        for (int i = 0; i < 16; i++) {
            int idx = tid + i * 256;
            int t = idx >> 10, r = (idx >> 3) & 127, u = idx & 7;
            const __nv_bfloat16* src = (t == 0) ? ah : (t == 1) ? al : (t == 2) ? bhp : blp;
            int grow = ((t < 2) ? bm : bn) + r;
            CPA16(sb + 1024 + buf * 65536 + t * 16384 + SWZ(r * 128 + u * 16),
                  src + (size_t)grow * 512 + kc * 64 + u * 8);
        }
        CPA_COMMIT();
    };

    stage(0, 0);
    stage(1, 1);
    for (int kc = 0; kc < 8; kc++) {
        int buf = kc % 3;
        if (kc >= 1) MBAR_WAIT(sb + 8, (kc - 1) & 1);
        if (kc + 2 < 8) stage(kc + 2, (kc + 2) % 3);
        if (kc < 6) CPA_WAIT2(); else if (kc == 6) CPA_WAIT1(); else CPA_WAIT0();
        FPROXY(); __syncthreads();
        if (wid == 0 && elect1()) {
            uint32_t ab = sb + 1024 + buf * 65536;
            uint64_t dah = dk(ab), dal = dk(ab + 16384);
            uint64_t dbh = dk(ab + 32768), dbl = dk(ab + 49152);
#pragma unroll
            for (int s = 0; s < 4; s++) mma16(tm, dah + 2*s, dbh + 2*s, ID_128, (kc > 0) || (s > 0));
#pragma unroll
            for (int s = 0; s < 4; s++) mma16(tm, dah + 2*s, dbl + 2*s, ID_128, 1);
#pragma unroll
            for (int s = 0; s < 4; s++) mma16(tm, dal + 2*s, dbh + 2*s, ID_128, 1);
            TC_COMMIT(sb + 8);
        }
    }
    MBAR_WAIT(sb + 8, 1);
    TC_FA();

    const int r = (wid & 3) * 32 + lane, cb = (wid >> 2) * 64;
    uint32_t u[64];
    LDTM32(u, tm + cb);
    LDTM32(u + 32, tm + cb + 32);
    TC_WLD(); TC_FB();
    float f[64];
#pragma unroll
    for (int j = 0; j < 64; j++)
        f[j] = scale * (__uint_as_float(u[j]) + bias[bn + cb + j]);
    if (mode == 1) {
        uint32_t hw[32], lw[32];
#pragma unroll
        for (int j = 0; j < 32; j++) {
            __nv_bfloat16 h0 = __float2bfloat16_rn(f[2*j]), h1 = __float2bfloat16_rn(f[2*j+1]);
            hw[j] = packh(h0, h1);
            lw[j] = packh(__float2bfloat16_rn(f[2*j]   - __bfloat162float(h0)),
                          __float2bfloat16_rn(f[2*j+1] - __bfloat162float(h1)));
        }
        size_t o = (size_t)(bm + r) * 512 + bn + cb;
#pragma unroll
        for (int g = 0; g < 8; g++) {
            *(uint4*)(ohp + o + g * 8) = make_uint4(hw[g*4], hw[g*4+1], hw[g*4+2], hw[g*4+3]);
            *(uint4*)(olp + o + g * 8) = make_uint4(lw[g*4], lw[g*4+1], lw[g*4+2], lw[g*4+3]);
        }
    } else {
#pragma unroll
        for (int j = 0; j < 64; j++) {
            __nv_bfloat16 h0 = __float2bfloat16_rn(f[j]);
            __nv_bfloat16 l0 = __float2bfloat16_rn(f[j] - __bfloat162float(h0));
            size_t o = (size_t)(bn + cb + j) * 4096 + bm + r;
            ohp[o] = h0;
            olp[o] = l0;
        }
    }
    __syncthreads();
    if (wid == 0) TC_DEALLOC(tm, 128);
}

// ------------------------- out-projection GEMM (fp32 out) ------------------
__global__ __launch_bounds__(256) void tgemm0(
    const __nv_bfloat16* __restrict__ ah, const __nv_bfloat16* __restrict__ al,
    const __nv_bfloat16* __restrict__ bh, const __nv_bfloat16* __restrict__ bl,
    const float* __restrict__ bias, float* __restrict__ of)
{
    extern __shared__ char sm[];
    const uint32_t sb = s2u(sm);
    const int tid = threadIdx.x, wid = tid >> 5, lane = tid & 31;
    const int bm = blockIdx.y * 128, bn = blockIdx.x * 128;

    if (wid == 0) { TC_ALLOC(sb, 128); TC_RELQ(); }
    if (tid == 0) MBAR_INIT(sb + 8, 1);
    __syncthreads();
    uint32_t tm;
    asm volatile("ld.shared.b32 %0, [%1];" : "=r"(tm) : "r"(sb));

    auto stage = [&](int kc, int buf) {
#pragma unroll
        for (int i = 0; i < 16; i++) {
            int idx = tid + i * 256;
            int t = idx >> 10, r = (idx >> 3) & 127, u = idx & 7;
            const __nv_bfloat16* src = (t == 0) ? ah : (t == 1) ? al : (t == 2) ? bh : bl;
            int grow = ((t < 2) ? bm : bn) + r;
            CPA16(sb + 1024 + buf * 65536 + t * 16384 + SWZ(r * 128 + u * 16),
                  src + (size_t)grow * 512 + kc * 64 + u * 8);
        }
        CPA_COMMIT();
    };

    stage(0, 0);
    stage(1, 1);
    for (int kc = 0; kc < 8; kc++) {
        int buf = kc % 3;
        if (kc >= 1) MBAR_WAIT(sb + 8, (kc - 1) & 1);
        if (kc + 2 < 8) stage(kc + 2, (kc + 2) % 3);
        if (kc < 6) CPA_WAIT2(); else if (kc == 6) CPA_WAIT1(); else CPA_WAIT0();
        FPROXY(); __syncthreads();
        if (wid == 0 && elect1()) {
            uint32_t ab = sb + 1024 + buf * 65536;
            uint64_t dah = dk(ab), dal = dk(ab + 16384);
            uint64_t dbh = dk(ab + 32768), dbl = dk(ab + 49152);
#pragma unroll
            for (int s = 0; s < 4; s++) mma16(tm, dah + 2*s, dbh + 2*s, ID_128, (kc > 0) || (s > 0));
#pragma unroll
            for (int s = 0; s < 4; s++) mma16(tm, dah + 2*s, dbl + 2*s, ID_128, 1);
#pragma unroll
            for (int s = 0; s < 4; s++) mma16(tm, dal + 2*s, dbh + 2*s, ID_128, 1);
            TC_COMMIT(sb + 8);
        }
    }
    MBAR_WAIT(sb + 8, 1);
    TC_FA();

    const int r = (wid & 3) * 32 + lane, cb = (wid >> 2) * 64;
    uint32_t u[64];
    LDTM32(u, tm + cb);
    LDTM32(u + 32, tm + cb + 32);
    TC_WLD(); TC_FB();
    float* p = of + (size_t)(bm + r) * 512 + bn + cb;
#pragma unroll
    for (int g = 0; g < 16; g++) {
        float4 o4;
        o4.x = __uint_as_float(u[g*4+0]) + bias[bn + cb + g*4+0];
        o4.y = __uint_as_float(u[g*4+1]) + bias[bn + cb + g*4+1];
        o4.z = __uint_as_float(u[g*4+2]) + bias[bn + cb + g*4+2];
        o4.w = __uint_as_float(u[g*4+3]) + bias[bn + cb + g*4+3];
        *(float4*)(p + g * 4) = o4;
    }
    __syncthreads();
    if (wid == 0) TC_DEALLOC(tm, 128);
}
#define GSM (1024 + 3 * 65536)

// ------------------------- pipelined tcgen05 attention (512 thr) -----------
#define A_Q   2048
#define A_K0  34816
#define A_V0  100352
#define A_PH  165888
#define A_PL  198656
#define A_SMEM 231424
#define NT 48

__global__ __launch_bounds__(512) void attn(
    const __nv_bfloat16* __restrict__ qh, const __nv_bfloat16* __restrict__ ql,
    const __nv_bfloat16* __restrict__ kh, const __nv_bfloat16* __restrict__ kl,
    const __nv_bfloat16* __restrict__ vth, const __nv_bfloat16* __restrict__ vtl,
    __nv_bfloat16* __restrict__ oh, __nv_bfloat16* __restrict__ ol)
{
    extern __shared__ char sm[];
    const uint32_t sb = s2u(sm);
    float* lsumf = (float*)(sm + 64);
    const int tid = threadIdx.x, wid = tid >> 5, lane = tid & 31;
    const int q0 = blockIdx.x * 128, h = blockIdx.y, b = blockIdx.z;

    if (wid == 0) { TC_ALLOC(sb, 512); TC_RELQ(); }
    if (tid == 0) {
        MBAR_INIT(sb + 8, 1);  MBAR_INIT(sb + 16, 1);
        MBAR_INIT(sb + 24, 512); MBAR_INIT(sb + 32, 512);
        MBAR_INIT(sb + 40, 512); MBAR_INIT(sb + 48, 512);
    }
    if (tid < 384) lsumf[tid] = 0.f;
    __syncthreads();
    uint32_t tm;
    asm volatile("ld.shared.b32 %0, [%1];" : "=r"(tm) : "r"(sb));
    const uint32_t tmo = tm + 256;

    auto ldK = [&](int g1, int buf) {       // 4 cp.async/thread -> kf[buf]
        int srcI = g1 >> 4, kt = g1 & 15;
        const size_t kvb = ((size_t)(srcI * 2 + b)) * 2048 * 512 + h * 64;
        uint32_t base = sb + A_K0 + buf * 32768;
#pragma unroll
        for (int i = 0; i < 4; i++) {
            int idx = tid + i * 512;
            int mat = idx >> 10, rem = idx & 1023;
            int rr = rem >> 3, u = rem & 7;
            const __nv_bfloat16* s0 = mat ? kl : kh;
            CPA16(base + mat * 16384 + SWZ(rr * 128 + u * 16),
                  s0 + kvb + (size_t)(kt * 128 + rr) * 512 + u * 8);
        }
        CPA_MBAR(sb + 24 + buf * 8);
    };
    auto ldV = [&](int g1, int buf) {       // 4 cp.async/thread -> vf[buf]
        int srcI = g1 >> 4, kt = g1 & 15;
        const size_t vtb = ((size_t)(srcI * 512 + h * 64)) * 4096 + b * 2048;
        uint32_t base = sb + A_V0 + buf * 32768;
#pragma unroll
        for (int i = 0; i < 4; i++) {
            int idx = tid + i * 512;
            int mat = idx >> 10, rem = idx & 1023;
            int d = rem >> 4, u = rem & 15;
            const __nv_bfloat16* s0 = mat ? vtl : vth;
            CPA16(base + mat * 16384 + (u >> 3) * 8192 + SWZ(d * 128 + (u & 7) * 16),
                  s0 + vtb + (size_t)d * 4096 + kt * 128 + u * 8);
        }
        CPA_MBAR(sb + 40 + buf * 8);
    };

    // Q tile hi/lo (once)
#pragma unroll
    for (int i = 0; i < 4; i++) {
        int idx = tid + i * 512;
        int t = idx >> 10, r = (idx >> 3) & 127, u = idx & 7;
        const __nv_bfloat16* src = t ? ql : qh;
        uint4 v = *(const uint4*)(src + (size_t)(b * 2048 + q0 + r) * 512 + h * 64 + u * 8);
        *(uint4*)(sm + A_Q + t * 16384 + SWZ(r * 128 + u * 16)) = v;
    }

    // prologue
    ldK(0, 0); ldV(0, 0); ldK(1, 1);
    FPROXY(); __syncthreads();
    if (wid == 0 && elect1()) {
        MBAR_WAIT(sb + 24, 0);
        FPROXY();
        uint64_t dqh = dk(sb + A_Q), dql = dk(sb + A_Q + 16384);
        uint64_t dkh = dk(sb + A_K0), dkl = dk(sb + A_K0 + 16384);
#pragma unroll
        for (int s = 0; s < 4; s++) mma16(tm, dqh + 2*s, dkh + 2*s, ID_128, s > 0);
#pragma unroll
        for (int s = 0; s < 4; s++) mma16(tm, dqh + 2*s, dkl + 2*s, ID_128, 1);
#pragma unroll
        for (int s = 0; s < 4; s++) mma16(tm, dql + 2*s, dkh + 2*s, ID_128, 1);
        TC_COMMIT(sb + 8);
    }

    const int r = (wid & 3) * 32 + lane;
    const int cb = (wid >> 2) * 32;     // 16 warps x 32 cols = 128

    for (int g = 0; g < NT; g++) {
        const int srcI = g >> 4;
        MBAR_WAIT(sb + 8, g & 1);                     // S(g) done
        TC_FA();
        if (g + 2 < NT) ldK(g + 2, g & 1);

        if (g + 1 < NT && wid == 0 && elect1()) {     // S(g+1) at top
            MBAR_WAIT(sb + 24 + ((g + 1) & 1) * 8, ((g + 1) >> 1) & 1);
            FPROXY();
            uint32_t kb = sb + A_K0 + ((g + 1) & 1) * 32768;
            uint64_t dqh = dk(sb + A_Q), dql = dk(sb + A_Q + 16384);
            uint64_t dkh = dk(kb), dkl = dk(kb + 16384);
            uint32_t tms = tm + ((g + 1) & 1) * 128;
#pragma unroll
            for (int s = 0; s < 4; s++) mma16(tms, dqh + 2*s, dkh + 2*s, ID_128, s > 0);
#pragma unroll
            for (int s = 0; s < 4; s++) mma16(tms, dqh + 2*s, dkl + 2*s, ID_128, 1);
#pragma unroll
            for (int s = 0; s < 4; s++) mma16(tms, dql + 2*s, dkh + 2*s, ID_128, 1);
            TC_COMMIT(sb + 8);
        }

        uint32_t u0[32];
        float ps = 0.0f;
        LDTM32(u0, tm + (g & 1) * 128 + cb);
        TC_WLD(); TC_FB();
#pragma unroll
        for (int j = 0; j < 16; j++) {
            float e0 = __expf(__uint_as_float(u0[2*j]));
            float e1 = __expf(__uint_as_float(u0[2*j + 1]));
            ps += e0 + e1;
            uint32_t hw = pack2(e0, e1);
            float h0 = __uint_as_float(hw << 16);
            float h1 = __uint_as_float(hw & 0xffff0000u);
            u0[2*j]     = hw;
            u0[2*j + 1] = pack2(e0 - h0, e1 - h1);
        }

        if (g >= 1) MBAR_WAIT(sb + 16, (g - 1) & 1);   // PV(g-1) done
        if (g + 1 < NT) ldV(g + 1, (g + 1) & 1);

#pragma unroll
        for (int j4 = 0; j4 < 8; j4++) {
            int t = cb + j4 * 4;
            uint32_t off = (uint32_t)((t >> 6) * 16384) + SWZ(r * 128 + (t & 63) * 2);
            *(uint2*)(sm + A_PH + off) = make_uint2(u0[j4*4],     u0[j4*4 + 2]);
            *(uint2*)(sm + A_PL + off) = make_uint2(u0[j4*4 + 1], u0[j4*4 + 3]);
        }
        atomicAdd(&lsumf[srcI * 128 + r], ps);
        FPROXY(); __syncthreads();

        if (wid == 0 && elect1()) {                    // PV(g)
            MBAR_WAIT(sb + 40 + (g & 1) * 8, (g >> 1) & 1);
            FPROXY();
            uint32_t vb0 = sb + A_V0 + (g & 1) * 32768;
            uint64_t dph = dk(sb + A_PH), dpl = dk(sb + A_PL);
            uint64_t dvh = dk(vb0), dvl = dk(vb0 + 16384);
            uint32_t dsto = tmo + srcI * 64;
            int accbase = (g & 15) > 0;
#pragma unroll
            for (int s = 0; s < 8; s++) {
                uint64_t pa = (uint64_t)((s >> 2) * 1024 + (s & 3) * 2);
                uint64_t vb = (uint64_t)((s >> 2) * 512  + (s & 3) * 2);
                mma16(dsto, dph + pa, dvh + vb, ID_PV, accbase || (s > 0));
            }
#pragma unroll
            for (int s = 0; s < 8; s++) {
                uint64_t pa = (uint64_t)((s >> 2) * 1024 + (s & 3) * 2);
                uint64_t vb = (uint64_t)((s >> 2) * 512  + (s & 3) * 2);
                mma16(dsto, dph + pa, dvl + vb, ID_PV, 1);
            }
#pragma unroll
            for (int s = 0; s < 8; s++) {
                uint64_t pa = (uint64_t)((s >> 2) * 1024 + (s & 3) * 2);
                uint64_t vb = (uint64_t)((s >> 2) * 512  + (s & 3) * 2);
                mma16(dsto, dpl + pa, dvh + vb, ID_PV, 1);
            }
            TC_COMMIT(sb + 16);
        }
    }

    MBAR_WAIT(sb + 16, (NT - 1) & 1);
    TC_FA();
    __syncthreads();

    if (wid < 8) {                       // epilogue: 8 warps
        const int cb2 = (wid >> 2) * 32;
        float oacc[32];
#pragma unroll
        for (int j = 0; j < 32; j++) oacc[j] = 0.0f;
#pragma unroll
        for (int srcI = 0; srcI < 3; srcI++) {
            uint32_t uo[32];
            LDTM32(uo, tmo + srcI * 64 + cb2);
            TC_WLD();
            float inv = 1.0f / lsumf[srcI * 128 + r];
#pragma unroll
            for (int j = 0; j < 32; j++) oacc[j] += __uint_as_float(uo[j]) * inv;
        }
        TC_FB();

        uint32_t hw[16], lw[16];
#pragma unroll
        for (int j = 0; j < 16; j++) {
            __nv_bfloat16 h0 = __float2bfloat16_rn(oacc[2*j]), h1 = __float2bfloat16_rn(oacc[2*j+1]);
            hw[j] = packh(h0, h1);
            lw[j] = packh(__float2bfloat16_rn(oacc[2*j]   - __bfloat162float(h0)),
                          __float2bfloat16_rn(oacc[2*j+1] - __bfloat162float(h1)));
        }
        size_t o = (size_t)(b * 2048 + q0 + r) * 512 + h * 64 + cb2;
#pragma unroll
        for (int g2 = 0; g2 < 4; g2++) {
            *(uint4*)(oh + o + g2 * 8) = make_uint4(hw[g2*4], hw[g2*4+1], hw[g2*4+2], hw[g2*4+3]);
            *(uint4*)(ol + o + g2 * 8) = make_uint4(lw[g2*4], lw[g2*4+1], lw[g2*4+2], lw[g2*4+3]);
        }
    }
    __syncthreads();
    if (wid == 0) TC_DEALLOC(tm, 512);
}

// ---------------------------------------------------------------------------
extern "C" void kernel_launch(void* const* d_in, const int* in_sizes, int n_in,
                              void* d_out, int out_size)
{
    const float* x  = (const float*)d_in[0];
    const float* y  = (const float*)d_in[1];
    const float* Wq = (const float*)d_in[2];
    const float* bq = (const float*)d_in[3];
    const float* Wk = (const float*)d_in[4];
    const float* bk = (const float*)d_in[5];
    const float* Wv = (const float*)d_in[6];
    const float* bv = (const float*)d_in[7];
    const float* Wp = (const float*)d_in[8];
    const float* bp = (const float*)d_in[9];
    float* out = (float*)d_out;

    __nv_bfloat16 *xh, *xl, *yh, *yl, *wh, *wl, *Qh, *Ql, *Kh, *Kl, *Vth, *Vtl, *Oh, *Ol;
    cudaGetSymbolAddress((void**)&xh, g_xh);  cudaGetSymbolAddress((void**)&xl, g_xl);
    cudaGetSymbolAddress((void**)&yh, g_yh);  cudaGetSymbolAddress((void**)&yl, g_yl);
    cudaGetSymbolAddress((void**)&wh, g_wh);  cudaGetSymbolAddress((void**)&wl, g_wl);
    cudaGetSymbolAddress((void**)&Qh, g_qh);  cudaGetSymbolAddress((void**)&Ql, g_ql);
    cudaGetSymbolAddress((void**)&Kh, g_kh);  cudaGetSymbolAddress((void**)&Kl, g_kl);
    cudaGetSymbolAddress((void**)&Vth, g_vth); cudaGetSymbolAddress((void**)&Vtl, g_vtl);
    cudaGetSymbolAddress((void**)&Oh, g_oh);  cudaGetSymbolAddress((void**)&Ol, g_ol);

    cudaFuncSetAttribute(proj,   cudaFuncAttributeMaxDynamicSharedMemorySize, GSM);
    cudaFuncSetAttribute(tgemm0, cudaFuncAttributeMaxDynamicSharedMemorySize, GSM);
    cudaFuncSetAttribute(attn,   cudaFuncAttributeMaxDynamicSharedMemorySize, A_SMEM);

    splitk<<<512, 256>>>(x, xh, xl, ELEM_X / 4);
    splitk<<<1024, 256>>>(y, yh, yl, ELEM_Y / 4);
    wtsk<<<dim3(16, 16, 1), dim3(32, 32)>>>(Wq, wh,            wl);
    wtsk<<<dim3(16, 16, 3), dim3(32, 32)>>>(Wk, wh + 1 * WSTR, wl + 1 * WSTR);
    wtsk<<<dim3(16, 16, 3), dim3(32, 32)>>>(Wv, wh + 4 * WSTR, wl + 4 * WSTR);
    wtsk<<<dim3(16, 16, 1), dim3(32, 32)>>>(Wp, wh + 7 * WSTR, wl + 7 * WSTR);

    proj<<<dim3(4, 32, 7), 256, GSM>>>(xh, xl, yh, yl, wh, wl, bq, bk, bv,
                                       Qh, Ql, Kh, Kl, Vth, Vtl);
    attn<<<dim3(16, 8, 2), 512, A_SMEM>>>(Qh, Ql, Kh, Kl, Vth, Vtl, Oh, Ol);
    tgemm0<<<dim3(4, 32), 256, GSM>>>(Oh, Ol, wh + 7 * WSTR, wl + 7 * WSTR, bp, out);
}